// round 10
// baseline (speedup 1.0000x reference)
#include <cuda_runtime.h>
#include <cuda_fp16.h>
#include <cstdint>
#include <cstddef>

#define D_MODEL 1024
#define D_FF    4096
#define HEADS   16
#define DKH     64
#define BATCH   2
#define SEQ     2048
#define NTOK    (BATCH*SEQ)
#define D3      (3*D_MODEL)

// ---------------- scratch (device globals; no allocations allowed) ----------
__device__ __half g_h1 [NTOK * D_MODEL];
__device__ __half g_qkv[NTOK * D3];
__device__ __half g_at [NTOK * D_MODEL];
__device__ float  g_x1 [NTOK * D_MODEL];
__device__ __half g_h2 [NTOK * D_MODEL];
__device__ __half g_f1 [NTOK * D_FF];
__device__ __half g_wqkv[D3 * D_MODEL];
__device__ __half g_wo[D_MODEL * D_MODEL];
__device__ __half g_w1[D_FF * D_MODEL];
__device__ __half g_w2[D_MODEL * D_FF];

// ---------------- helpers ---------------------------------------------------
__device__ __forceinline__ uint32_t smem_u32(const void* p) {
    return (uint32_t)__cvta_generic_to_shared(p);
}
#define CP_ASYNC16(dst, src) \
    asm volatile("cp.async.cg.shared.global [%0], [%1], 16;\n" :: "r"(dst), "l"(src))
#define CP_COMMIT() asm volatile("cp.async.commit_group;\n" ::: "memory")
#define CP_WAIT(n)  asm volatile("cp.async.wait_group %0;\n" :: "n"(n) : "memory")

#define MMA_F16(d, a, b) \
    asm volatile("mma.sync.aligned.m16n8k16.row.col.f32.f16.f16.f32 " \
                 "{%0,%1,%2,%3},{%4,%5,%6,%7},{%8,%9},{%0,%1,%2,%3};" \
                 : "+f"(d[0]), "+f"(d[1]), "+f"(d[2]), "+f"(d[3]) \
                 : "r"(a[0]), "r"(a[1]), "r"(a[2]), "r"(a[3]), \
                   "r"(b[0]), "r"(b[1]))

#define LDMX4(r0, r1, r2, r3, addr) \
    asm volatile("ldmatrix.sync.aligned.m8n8.x4.shared.b16 {%0,%1,%2,%3}, [%4];" \
                 : "=r"(r0), "=r"(r1), "=r"(r2), "=r"(r3) : "r"(addr))
#define LDMX4_TRANS(r0, r1, r2, r3, addr) \
    asm volatile("ldmatrix.sync.aligned.m8n8.x4.trans.shared.b16 {%0,%1,%2,%3}, [%4];" \
                 : "=r"(r0), "=r"(r1), "=r"(r2), "=r"(r3) : "r"(addr))

// ---------------- weight conversion -----------------------------------------
__global__ __launch_bounds__(256) void conv_half(const float4* __restrict__ in,
                                                 __half* __restrict__ out, int n4)
{
    int i = blockIdx.x * 256 + threadIdx.x;
    if (i < n4) {
        float4 v = in[i];
        __half2* o = (__half2*)(out + (size_t)i * 4);
        o[0] = __floats2half2_rn(v.x, v.y);
        o[1] = __floats2half2_rn(v.z, v.w);
    }
}

__global__ __launch_bounds__(256) void conv_qkv(const float4* __restrict__ q,
                                                const float4* __restrict__ k,
                                                const float4* __restrict__ v,
                                                __half* __restrict__ out)
{
    const int per = D_MODEL * D_MODEL / 4;
    int i = blockIdx.x * 256 + threadIdx.x;
    float4 val;
    if (i < per)            val = q[i];
    else if (i < 2 * per)   val = k[i - per];
    else                    val = v[i - 2 * per];
    __half2* o = (__half2*)(out + (size_t)i * 4);
    o[0] = __floats2half2_rn(val.x, val.y);
    o[1] = __floats2half2_rn(val.z, val.w);
}

// ---------------- LayerNorm (fp32 in, fp16 out) -----------------------------
__global__ __launch_bounds__(256) void ln_kernel(const float* __restrict__ x,
                                                 const float* __restrict__ g,
                                                 const float* __restrict__ b,
                                                 __half* __restrict__ out)
{
    __shared__ float red[8];
    __shared__ float bcast;
    const int row = blockIdx.x;
    const int t = threadIdx.x;
    const int lane = t & 31, w = t >> 5;

    const float4* x4 = (const float4*)x + (size_t)row * 256;
    float4 v = x4[t];

    float s = v.x + v.y + v.z + v.w;
    #pragma unroll
    for (int o = 16; o; o >>= 1) s += __shfl_xor_sync(0xffffffffu, s, o);
    if (lane == 0) red[w] = s;
    __syncthreads();
    if (t == 0) {
        float tot = 0.f;
        #pragma unroll
        for (int i = 0; i < 8; i++) tot += red[i];
        bcast = tot * (1.f / 1024.f);
    }
    __syncthreads();
    const float mu = bcast;

    float4 d = make_float4(v.x - mu, v.y - mu, v.z - mu, v.w - mu);
    float vs = d.x*d.x + d.y*d.y + d.z*d.z + d.w*d.w;
    __syncthreads();
    #pragma unroll
    for (int o = 16; o; o >>= 1) vs += __shfl_xor_sync(0xffffffffu, vs, o);
    if (lane == 0) red[w] = vs;
    __syncthreads();
    if (t == 0) {
        float tot = 0.f;
        #pragma unroll
        for (int i = 0; i < 8; i++) tot += red[i];
        bcast = rsqrtf(tot * (1.f / 1024.f) + 1e-5f);
    }
    __syncthreads();
    const float rs = bcast;

    float4 gv = ((const float4*)g)[t];
    float4 bv = ((const float4*)b)[t];
    __half2* orow = (__half2*)(out + (size_t)row * 1024);
    orow[t*2]   = __floats2half2_rn(d.x*rs*gv.x + bv.x, d.y*rs*gv.y + bv.y);
    orow[t*2+1] = __floats2half2_rn(d.z*rs*gv.z + bv.z, d.w*rs*gv.w + bv.w);
}

// ---------------- FP16 tensor-core GEMM NT (256x128 CTA tile) ---------------
// C[N,M] = A[N,K] * B[M,K]^T.  CTA: 256 token rows x 128 feature cols, BK=32.
// 8 warps in 4x2 grid, warp tile 64x64 (4x8 m16n8k16 frags -> mma:ldm = 4.0).
// cp.async double-buffered (dynamic smem, 60KB), ldmatrix.x4 fragments.
// EPI: 0=none, 1=+bias, 2=+res, 3=relu(+bias)+res.  HOUT: 1 = store half.
#define GLDSH 40                    // 32 + 8 pad halves; 80B rows
#define G_ASTG (256*GLDSH)          // halves per A stage
#define G_BSTG (128*GLDSH)          // halves per B stage
#define G_SMEM ((2*G_ASTG + 2*G_BSTG) * 2)   // bytes = 61440

template<int EPI, int HOUT>
__global__ __launch_bounds__(256, 1) void gemm_f16(const __half* __restrict__ A,
                                                   const __half* __restrict__ B,
                                                   void* __restrict__ Cv,
                                                   int N, int M, int K,
                                                   const float* __restrict__ bias,
                                                   const float* __restrict__ res)
{
    extern __shared__ __align__(16) char sh[];
    __half* Ash = (__half*)sh;                 // [2][256][GLDSH]
    __half* Bsh = (__half*)sh + 2 * G_ASTG;    // [2][128][GLDSH]

    const int t    = threadIdx.x;
    const int lane = t & 31;
    const int warp = t >> 5;
    const int wm   = warp >> 1;          // 0..3  (64-row slice)
    const int wn   = warp & 1;           // 0..1  (64-col slice)
    const int g    = lane >> 2;
    const int tig  = lane & 3;
    const int n0   = blockIdx.y * 256;   // token rows
    const int m0   = blockIdx.x * 128;   // feature cols

    // ldmatrix lane->element maps
    const int a_row = lane & 15;
    const int a_col = (lane >> 4) << 3;
    const int b_row = ((lane >> 4) << 3) + (lane & 7);
    const int b_col = ((lane >> 3) & 1) << 3;

    // global-load mapping: A row = t (4 chunks), B row = t>>1 (2 chunks)
    const int brow = t >> 1;
    const int bch  = (t & 1) * 2;

    const __half* Ar = A + (size_t)(n0 + t) * K;
    const __half* Br = B + (size_t)(m0 + brow) * K + bch * 8;

    float acc[4][8][4];
    #pragma unroll
    for (int i = 0; i < 4; i++)
        #pragma unroll
        for (int j = 0; j < 8; j++)
            #pragma unroll
            for (int c = 0; c < 4; c++) acc[i][j][c] = 0.f;

    const int nK = K / 32;

    // prologue: stage 0
    {
        __half* As = Ash;  __half* Bs = Bsh;
        #pragma unroll
        for (int c = 0; c < 4; c++)
            CP_ASYNC16(smem_u32(&As[t * GLDSH + c * 8]), Ar + c * 8);
        #pragma unroll
        for (int c = 0; c < 2; c++)
            CP_ASYNC16(smem_u32(&Bs[brow * GLDSH + (bch + c) * 8]), Br + c * 8);
        CP_COMMIT();
    }

    for (int kt = 0; kt < nK; kt++) {
        const int cur = kt & 1;
        if (kt + 1 < nK) {
            const int nxt = cur ^ 1;
            const int ko = (kt + 1) * 32;
            __half* As = Ash + nxt * G_ASTG;
            __half* Bs = Bsh + nxt * G_BSTG;
            #pragma unroll
            for (int c = 0; c < 4; c++)
                CP_ASYNC16(smem_u32(&As[t * GLDSH + c * 8]), Ar + ko + c * 8);
            #pragma unroll
            for (int c = 0; c < 2; c++)
                CP_ASYNC16(smem_u32(&Bs[brow * GLDSH + (bch + c) * 8]), Br + ko + c * 8);
            CP_COMMIT();
            CP_WAIT(1);
        } else {
            CP_WAIT(0);
        }
        __syncthreads();

        const __half* As = Ash + cur * G_ASTG;
        const __half* Bs = Bsh + cur * G_BSTG;

        #pragma unroll
        for (int ks = 0; ks < 2; ks++) {
            const int kc = ks * 16;
            uint32_t af[4][4];
            #pragma unroll
            for (int mt = 0; mt < 4; mt++) {
                const int r = wm * 64 + mt * 16;
                LDMX4(af[mt][0], af[mt][1], af[mt][2], af[mt][3],
                      smem_u32(&As[(r + a_row) * GLDSH + kc + a_col]));
            }
            uint32_t bf[8][2];
            #pragma unroll
            for (int p = 0; p < 4; p++) {
                const int c = wn * 64 + p * 16;
                uint32_t r0, r1, r2, r3;
                LDMX4(r0, r1, r2, r3,
                      smem_u32(&Bs[(c + b_row) * GLDSH + kc + b_col]));
                bf[2*p][0] = r0;  bf[2*p][1] = r1;
                bf[2*p+1][0] = r2; bf[2*p+1][1] = r3;
            }
            #pragma unroll
            for (int mt = 0; mt < 4; mt++)
                #pragma unroll
                for (int nt = 0; nt < 8; nt++)
                    MMA_F16(acc[mt][nt], af[mt], bf[nt]);
        }
        __syncthreads();
    }

    #pragma unroll
    for (int mt = 0; mt < 4; mt++) {
        const int r0 = n0 + wm * 64 + mt * 16 + g;
        #pragma unroll
        for (int nt = 0; nt < 8; nt++) {
            const int col = m0 + wn * 64 + nt * 8 + 2 * tig;
            float2 v0 = make_float2(acc[mt][nt][0], acc[mt][nt][1]);
            float2 v1 = make_float2(acc[mt][nt][2], acc[mt][nt][3]);
            if (EPI == 1 || EPI == 3) {
                float2 bb = *(const float2*)&bias[col];
                v0.x += bb.x; v0.y += bb.y;
                v1.x += bb.x; v1.y += bb.y;
            }
            if (EPI == 3) {
                v0.x = fmaxf(v0.x, 0.f); v0.y = fmaxf(v0.y, 0.f);
                v1.x = fmaxf(v1.x, 0.f); v1.y = fmaxf(v1.y, 0.f);
            }
            if (EPI == 2 || EPI == 3) {
                float2 r0v = *(const float2*)&res[(size_t)r0 * M + col];
                float2 r1v = *(const float2*)&res[(size_t)(r0 + 8) * M + col];
                v0.x += r0v.x; v0.y += r0v.y;
                v1.x += r1v.x; v1.y += r1v.y;
            }
            if (HOUT) {
                __half* C = (__half*)Cv;
                *(__half2*)&C[(size_t)r0 * M + col]       = __floats2half2_rn(v0.x, v0.y);
                *(__half2*)&C[(size_t)(r0 + 8) * M + col] = __floats2half2_rn(v1.x, v1.y);
            } else {
                float* C = (float*)Cv;
                *(float2*)&C[(size_t)r0 * M + col]       = v0;
                *(float2*)&C[(size_t)(r0 + 8) * M + col] = v1;
            }
        }
    }
}

// ---------------- FP16 tensor-core flash attention (round-7, proven) --------
#define HQS  0
#define HKS  9216
#define HVS  18432
#define HPS  27648
#define HTOT 36864
#define AMSK_B (HTOT*2)
#define ASMEM_BYTES (AMSK_B + 2*64*4)
#define KSTG 4608

__global__ __launch_bounds__(256) void attn_tc(const __half* __restrict__ QKV,
                                               const unsigned char* __restrict__ mask,
                                               __half* __restrict__ O)
{
    extern __shared__ char shb[];
    __half* Qs  = (__half*)shb + HQS;
    __half* Ks  = (__half*)shb + HKS;
    __half* Vs  = (__half*)shb + HVS;
    __half* Ps  = (__half*)shb + HPS;
    float*  msk = (float*)(shb + AMSK_B);

    const int t    = threadIdx.x;
    const int lane = t & 31;
    const int warp = t >> 5;
    const int g    = lane >> 2;
    const int tig  = lane & 3;
    const int q0   = blockIdx.x * 128;
    const int h    = blockIdx.y;
    const int b    = blockIdx.z;
    const size_t baseQ = (size_t)b * SEQ * D3 + (size_t)h * DKH;
    const size_t baseK = baseQ + D_MODEL;
    const size_t baseV = baseQ + 2 * D_MODEL;
    const size_t baseO = (size_t)b * SEQ * D_MODEL + (size_t)h * DKH;
    const int rA = warp * 16 + g;

    const int a_row = lane & 15;
    const int a_col = (lane >> 4) << 3;
    const int b_row = ((lane >> 4) << 3) + (lane & 7);
    const int b_col = ((lane >> 3) & 1) << 3;

    #pragma unroll
    for (int i = 0; i < 4; i++) {
        int idx = t + i * 256, row = idx >> 3, s8 = (idx & 7) * 8;
        CP_ASYNC16(smem_u32(&Qs[row * 72 + s8]),
                   &QKV[baseQ + (size_t)(q0 + row) * D3 + s8]);
    }
    #pragma unroll
    for (int i = 0; i < 2; i++) {
        int idx = t + i * 256, row = idx >> 3, s8 = (idx & 7) * 8;
        CP_ASYNC16(smem_u32(&Ks[row * 72 + s8]),
                   &QKV[baseK + (size_t)row * D3 + s8]);
        CP_ASYNC16(smem_u32(&Vs[row * 72 + s8]),
                   &QKV[baseV + (size_t)row * D3 + s8]);
    }
    if (t < 64) msk[t] = mask[(size_t)b * SEQ + t] ? -3.0e38f : 0.f;
    CP_COMMIT();
    CP_WAIT(0);
    __syncthreads();

    uint32_t qf[4][4];
    #pragma unroll
    for (int kc4 = 0; kc4 < 4; kc4++) {
        LDMX4(qf[kc4][0], qf[kc4][1], qf[kc4][2], qf[kc4][3],
              smem_u32(&Qs[(warp * 16 + a_row) * 72 + kc4 * 16 + a_col]));
    }

    float m0 = -3.0e38f, m1 = -3.0e38f, l0 = 0.f, l1 = 0.f;
    float oacc[8][4];
    #pragma unroll
    for (int nt = 0; nt < 8; nt++)
        #pragma unroll
        for (int c = 0; c < 4; c++) oacc[nt][c] = 0.f;

    const int ntiles = SEQ / 64;
    for (int kt = 0; kt < ntiles; kt++) {
        const int cur = kt & 1;
        const bool pref = (kt + 1 < ntiles);
        if (pref) {
            const int nxt = cur ^ 1;
            const int k0n = (kt + 1) * 64;
            #pragma unroll
            for (int i = 0; i < 2; i++) {
                int idx = t + i * 256, row = idx >> 3, s8 = (idx & 7) * 8;
                CP_ASYNC16(smem_u32(&Ks[nxt * KSTG + row * 72 + s8]),
                           &QKV[baseK + (size_t)(k0n + row) * D3 + s8]);
                CP_ASYNC16(smem_u32(&Vs[nxt * KSTG + row * 72 + s8]),
                           &QKV[baseV + (size_t)(k0n + row) * D3 + s8]);
            }
            if (t < 64) msk[nxt * 64 + t] =
                mask[(size_t)b * SEQ + k0n + t] ? -3.0e38f : 0.f;
            CP_COMMIT();
        }
        const __half* Kc = Ks + cur * KSTG;
        const __half* Vc = Vs + cur * KSTG;
        const float*  mc = msk + cur * 64;

        float sc[8][4];
        #pragma unroll
        for (int nt = 0; nt < 8; nt++)
            #pragma unroll
            for (int c = 0; c < 4; c++) sc[nt][c] = 0.f;

        #pragma unroll
        for (int kc4 = 0; kc4 < 4; kc4++) {
            const int kc = kc4 * 16;
            #pragma unroll
            for (int p = 0; p < 4; p++) {
                const int c = p * 16;
                uint32_t r0, r1, r2, r3;
                LDMX4(r0, r1, r2, r3,
                      smem_u32(&Kc[(c + b_row) * 72 + kc + b_col]));
                uint32_t b0[2] = {r0, r1};
                uint32_t b1[2] = {r2, r3};
                MMA_F16(sc[2*p],     qf[kc4], b0);
                MMA_F16(sc[2*p + 1], qf[kc4], b1);
            }
        }

        float tm0 = -3.0e38f, tm1 = -3.0e38f;
        #pragma unroll
        for (int nt = 0; nt < 8; nt++) {
            const float mk0 = mc[nt * 8 + 2 * tig];
            const float mk1 = mc[nt * 8 + 2 * tig + 1];
            sc[nt][0] = sc[nt][0] * 0.125f + mk0;
            sc[nt][1] = sc[nt][1] * 0.125f + mk1;
            sc[nt][2] = sc[nt][2] * 0.125f + mk0;
            sc[nt][3] = sc[nt][3] * 0.125f + mk1;
            tm0 = fmaxf(tm0, fmaxf(sc[nt][0], sc[nt][1]));
            tm1 = fmaxf(tm1, fmaxf(sc[nt][2], sc[nt][3]));
        }
        tm0 = fmaxf(tm0, __shfl_xor_sync(0xffffffffu, tm0, 1));
        tm0 = fmaxf(tm0, __shfl_xor_sync(0xffffffffu, tm0, 2));
        tm1 = fmaxf(tm1, __shfl_xor_sync(0xffffffffu, tm1, 1));
        tm1 = fmaxf(tm1, __shfl_xor_sync(0xffffffffu, tm1, 2));

        const float nm0 = fmaxf(m0, tm0), nm1 = fmaxf(m1, tm1);
        const float a0 = __expf(m0 - nm0), a1 = __expf(m1 - nm1);

        float ps0 = 0.f, ps1 = 0.f;
        #pragma unroll
        for (int nt = 0; nt < 8; nt++) {
            const float p0 = __expf(sc[nt][0] - nm0);
            const float p1 = __expf(sc[nt][1] - nm0);
            const float p2 = __expf(sc[nt][2] - nm1);
            const float p3 = __expf(sc[nt][3] - nm1);
            ps0 += p0 + p1; ps1 += p2 + p3;
            *(__half2*)&Ps[rA * 72 + nt * 8 + 2*tig]       = __floats2half2_rn(p0, p1);
            *(__half2*)&Ps[(rA + 8) * 72 + nt * 8 + 2*tig] = __floats2half2_rn(p2, p3);
        }
        ps0 += __shfl_xor_sync(0xffffffffu, ps0, 1);
        ps0 += __shfl_xor_sync(0xffffffffu, ps0, 2);
        ps1 += __shfl_xor_sync(0xffffffffu, ps1, 1);
        ps1 += __shfl_xor_sync(0xffffffffu, ps1, 2);

        l0 = l0 * a0 + ps0;  l1 = l1 * a1 + ps1;
        m0 = nm0;  m1 = nm1;
        #pragma unroll
        for (int nt = 0; nt < 8; nt++) {
            oacc[nt][0] *= a0; oacc[nt][1] *= a0;
            oacc[nt][2] *= a1; oacc[nt][3] *= a1;
        }
        __syncwarp();

        const int mi = lane >> 3, rr = lane & 7;
        #pragma unroll
        for (int kc4 = 0; kc4 < 4; kc4++) {
            const int kc = kc4 * 16;
            uint32_t af[4];
            LDMX4(af[0], af[1], af[2], af[3],
                  smem_u32(&Ps[(warp * 16 + a_row) * 72 + kc + a_col]));
            #pragma unroll
            for (int ntp = 0; ntp < 4; ntp++) {
                const int key = kc + ((mi & 1) << 3) + rr;
                const int dim = ntp * 16 + ((mi >> 1) << 3);
                uint32_t r0, r1, r2, r3;
                LDMX4_TRANS(r0, r1, r2, r3, smem_u32(&Vc[key * 72 + dim]));
                uint32_t b0[2] = {r0, r1};
                uint32_t b1[2] = {r2, r3};
                MMA_F16(oacc[2*ntp],     af, b0);
                MMA_F16(oacc[2*ntp + 1], af, b1);
            }
        }

        if (pref) CP_WAIT(0);
        __syncthreads();
    }

    const float i0 = 1.f / l0, i1 = 1.f / l1;
    #pragma unroll
    for (int nt = 0; nt < 8; nt++) {
        const int col = nt * 8 + 2 * tig;
        *(__half2*)&O[baseO + (size_t)(q0 + rA) * D_MODEL + col] =
            __floats2half2_rn(oacc[nt][0] * i0, oacc[nt][1] * i0);
        *(__half2*)&O[baseO + (size_t)(q0 + rA + 8) * D_MODEL + col] =
            __floats2half2_rn(oacc[nt][2] * i1, oacc[nt][3] * i1);
    }
}

// ---------------- launch ---------------------------------------------------
extern "C" void kernel_launch(void* const* d_in, const int* in_sizes, int n_in,
                              void* d_out, int out_size)
{
    const float* x     = (const float*)d_in[0];
    const unsigned char* mask = (const unsigned char*)d_in[1];
    const float* W_Q   = (const float*)d_in[2];
    const float* W_K   = (const float*)d_in[3];
    const float* W_V   = (const float*)d_in[4];
    const float* W_O   = (const float*)d_in[5];
    const float* W1    = (const float*)d_in[6];
    const float* b1    = (const float*)d_in[7];
    const float* W2    = (const float*)d_in[8];
    const float* b2    = (const float*)d_in[9];
    const float* g1    = (const float*)d_in[10];
    const float* beta1 = (const float*)d_in[11];
    const float* g2    = (const float*)d_in[12];
    const float* beta2 = (const float*)d_in[13];
    float* out = (float*)d_out;

    __half *h1, *qkv, *at, *h2, *f1;
    __half *wqkv, *wo, *w1, *w2;
    float *x1;
    cudaGetSymbolAddress((void**)&h1,   g_h1);
    cudaGetSymbolAddress((void**)&qkv,  g_qkv);
    cudaGetSymbolAddress((void**)&at,   g_at);
    cudaGetSymbolAddress((void**)&x1,   g_x1);
    cudaGetSymbolAddress((void**)&h2,   g_h2);
    cudaGetSymbolAddress((void**)&f1,   g_f1);
    cudaGetSymbolAddress((void**)&wqkv, g_wqkv);
    cudaGetSymbolAddress((void**)&wo,   g_wo);
    cudaGetSymbolAddress((void**)&w1,   g_w1);
    cudaGetSymbolAddress((void**)&w2,   g_w2);

    cudaFuncSetAttribute(attn_tc, cudaFuncAttributeMaxDynamicSharedMemorySize,
                         ASMEM_BYTES);
    cudaFuncSetAttribute(gemm_f16<0,1>, cudaFuncAttributeMaxDynamicSharedMemorySize, G_SMEM);
    cudaFuncSetAttribute(gemm_f16<2,0>, cudaFuncAttributeMaxDynamicSharedMemorySize, G_SMEM);
    cudaFuncSetAttribute(gemm_f16<1,1>, cudaFuncAttributeMaxDynamicSharedMemorySize, G_SMEM);
    cudaFuncSetAttribute(gemm_f16<3,0>, cudaFuncAttributeMaxDynamicSharedMemorySize, G_SMEM);

    const dim3 gQKV(D3/128,      NTOK/256);  // (24, 16)
    const dim3 gDD (D_MODEL/128, NTOK/256);  // (8, 16)
    const dim3 gDF (D_FF/128,    NTOK/256);  // (32, 16)
    const int DD4 = D_MODEL*D_MODEL/4, DF4 = D_FF*D_MODEL/4;

    // 0. weights -> fp16
    conv_qkv <<<3*DD4/256, 256>>>((const float4*)W_Q, (const float4*)W_K,
                                  (const float4*)W_V, wqkv);
    conv_half<<<(DD4+255)/256, 256>>>((const float4*)W_O, wo, DD4);
    conv_half<<<(DF4+255)/256, 256>>>((const float4*)W1,  w1, DF4);
    conv_half<<<(DF4+255)/256, 256>>>((const float4*)W2,  w2, DF4);

    // 1. pre-LN
    ln_kernel<<<NTOK, 256>>>(x, g1, beta1, h1);
    // 2. fused QKV projection
    gemm_f16<0,1><<<gQKV, 256, G_SMEM>>>(h1, wqkv, qkv, NTOK, D3, D_MODEL, nullptr, nullptr);
    // 3. flash attention
    attn_tc<<<dim3(SEQ/128, HEADS, BATCH), 256, ASMEM_BYTES>>>(qkv, mask, at);
    // 4. output projection + residual (fp32 out)
    gemm_f16<2,0><<<gDD, 256, G_SMEM>>>(at, wo, x1, NTOK, D_MODEL, D_MODEL, nullptr, x);
    // 5. second LN
    ln_kernel<<<NTOK, 256>>>(x1, g2, beta2, h2);
    // 6. FFN1 (+b1)
    gemm_f16<1,1><<<gDF, 256, G_SMEM>>>(h2, w1, f1, NTOK, D_FF, D_MODEL, b1, nullptr);
    // 7. FFN2: relu(C + b2) + residual(x1), fp32 final
    gemm_f16<3,0><<<gDD, 256, G_SMEM>>>(f1, w2, out, NTOK, D_MODEL, D_FF, b2, x1);
}

// round 11
// speedup vs baseline: 1.0691x; 1.0691x over previous
#include <cuda_runtime.h>
#include <cuda_fp16.h>
#include <cstdint>
#include <cstddef>

#define D_MODEL 1024
#define D_FF    4096
#define HEADS   16
#define DKH     64
#define BATCH   2
#define SEQ     2048
#define NTOK    (BATCH*SEQ)
#define D3      (3*D_MODEL)

// ---------------- scratch (device globals; no allocations allowed) ----------
__device__ __half g_h1 [NTOK * D_MODEL];
__device__ __half g_qkv[NTOK * D3];
__device__ __half g_at [NTOK * D_MODEL];
__device__ float  g_x1 [NTOK * D_MODEL];
__device__ __half g_h2 [NTOK * D_MODEL];
__device__ __half g_f1 [NTOK * D_FF];
__device__ __half g_wqkv[D3 * D_MODEL];
__device__ __half g_wo[D_MODEL * D_MODEL];
__device__ __half g_w1[D_FF * D_MODEL];
__device__ __half g_w2[D_MODEL * D_FF];

// ---------------- helpers ---------------------------------------------------
__device__ __forceinline__ uint32_t smem_u32(const void* p) {
    return (uint32_t)__cvta_generic_to_shared(p);
}
#define CP_ASYNC16(dst, src) \
    asm volatile("cp.async.cg.shared.global [%0], [%1], 16;\n" :: "r"(dst), "l"(src))
#define CP_COMMIT() asm volatile("cp.async.commit_group;\n" ::: "memory")
#define CP_WAIT(n)  asm volatile("cp.async.wait_group %0;\n" :: "n"(n) : "memory")

#define MMA_F16(d, a, b) \
    asm volatile("mma.sync.aligned.m16n8k16.row.col.f32.f16.f16.f32 " \
                 "{%0,%1,%2,%3},{%4,%5,%6,%7},{%8,%9},{%0,%1,%2,%3};" \
                 : "+f"(d[0]), "+f"(d[1]), "+f"(d[2]), "+f"(d[3]) \
                 : "r"(a[0]), "r"(a[1]), "r"(a[2]), "r"(a[3]), \
                   "r"(b[0]), "r"(b[1]))

#define LDMX4(r0, r1, r2, r3, addr) \
    asm volatile("ldmatrix.sync.aligned.m8n8.x4.shared.b16 {%0,%1,%2,%3}, [%4];" \
                 : "=r"(r0), "=r"(r1), "=r"(r2), "=r"(r3) : "r"(addr))
#define LDMX4_TRANS(r0, r1, r2, r3, addr) \
    asm volatile("ldmatrix.sync.aligned.m8n8.x4.trans.shared.b16 {%0,%1,%2,%3}, [%4];" \
                 : "=r"(r0), "=r"(r1), "=r"(r2), "=r"(r3) : "r"(addr))

// ---------------- weight conversion -----------------------------------------
__global__ __launch_bounds__(256) void conv_half(const float4* __restrict__ in,
                                                 __half* __restrict__ out, int n4)
{
    int i = blockIdx.x * 256 + threadIdx.x;
    if (i < n4) {
        float4 v = in[i];
        __half2* o = (__half2*)(out + (size_t)i * 4);
        o[0] = __floats2half2_rn(v.x, v.y);
        o[1] = __floats2half2_rn(v.z, v.w);
    }
}

__global__ __launch_bounds__(256) void conv_qkv(const float4* __restrict__ q,
                                                const float4* __restrict__ k,
                                                const float4* __restrict__ v,
                                                __half* __restrict__ out)
{
    const int per = D_MODEL * D_MODEL / 4;
    int i = blockIdx.x * 256 + threadIdx.x;
    float4 val;
    if (i < per)            val = q[i];
    else if (i < 2 * per)   val = k[i - per];
    else                    val = v[i - 2 * per];
    __half2* o = (__half2*)(out + (size_t)i * 4);
    o[0] = __floats2half2_rn(val.x, val.y);
    o[1] = __floats2half2_rn(val.z, val.w);
}

// ---------------- LayerNorm (fp32 in, fp16 out) -----------------------------
__global__ __launch_bounds__(256) void ln_kernel(const float* __restrict__ x,
                                                 const float* __restrict__ g,
                                                 const float* __restrict__ b,
                                                 __half* __restrict__ out)
{
    __shared__ float red[8];
    __shared__ float bcast;
    const int row = blockIdx.x;
    const int t = threadIdx.x;
    const int lane = t & 31, w = t >> 5;

    const float4* x4 = (const float4*)x + (size_t)row * 256;
    float4 v = x4[t];

    float s = v.x + v.y + v.z + v.w;
    #pragma unroll
    for (int o = 16; o; o >>= 1) s += __shfl_xor_sync(0xffffffffu, s, o);
    if (lane == 0) red[w] = s;
    __syncthreads();
    if (t == 0) {
        float tot = 0.f;
        #pragma unroll
        for (int i = 0; i < 8; i++) tot += red[i];
        bcast = tot * (1.f / 1024.f);
    }
    __syncthreads();
    const float mu = bcast;

    float4 d = make_float4(v.x - mu, v.y - mu, v.z - mu, v.w - mu);
    float vs = d.x*d.x + d.y*d.y + d.z*d.z + d.w*d.w;
    __syncthreads();
    #pragma unroll
    for (int o = 16; o; o >>= 1) vs += __shfl_xor_sync(0xffffffffu, vs, o);
    if (lane == 0) red[w] = vs;
    __syncthreads();
    if (t == 0) {
        float tot = 0.f;
        #pragma unroll
        for (int i = 0; i < 8; i++) tot += red[i];
        bcast = rsqrtf(tot * (1.f / 1024.f) + 1e-5f);
    }
    __syncthreads();
    const float rs = bcast;

    float4 gv = ((const float4*)g)[t];
    float4 bv = ((const float4*)b)[t];
    __half2* orow = (__half2*)(out + (size_t)row * 1024);
    orow[t*2]   = __floats2half2_rn(d.x*rs*gv.x + bv.x, d.y*rs*gv.y + bv.y);
    orow[t*2+1] = __floats2half2_rn(d.z*rs*gv.z + bv.z, d.w*rs*gv.w + bv.w);
}

// ---------------- FP16 tensor-core GEMM NT (128x128, BK=64) -----------------
// C[N,M] = A[N,K] * B[M,K]^T.  128x128 tile, BK=64 halves (128B rows), 256
// thr, 2x4 warps, 64x32/warp via 4x4 m16n8k16.  cp.async double-buffered
// (dynamic smem 72KB -> still 2 CTA/SM), ldmatrix.x4 fragments.
// EPI: 0=none, 1=+bias, 2=+res, 3=relu(+bias)+res.  HOUT: 1 = store half.
#define GLDSH 72                     // 64 + 8 pad halves; 144B rows
#define G_STG (128*GLDSH)            // halves per stage per matrix
#define G_SMEM (4*G_STG*2)           // bytes = 73728

template<int EPI, int HOUT>
__global__ __launch_bounds__(256) void gemm_f16(const __half* __restrict__ A,
                                                const __half* __restrict__ B,
                                                void* __restrict__ Cv,
                                                int N, int M, int K,
                                                const float* __restrict__ bias,
                                                const float* __restrict__ res)
{
    extern __shared__ __align__(16) char sh[];
    __half* Ash = (__half*)sh;                // [2][128][72]
    __half* Bsh = (__half*)sh + 2 * G_STG;    // [2][128][72]

    const int t    = threadIdx.x;
    const int lane = t & 31;
    const int warp = t >> 5;
    const int wm   = warp >> 2;
    const int wn   = warp & 3;
    const int g    = lane >> 2;
    const int tig  = lane & 3;
    const int n0   = blockIdx.y * 128;
    const int m0   = blockIdx.x * 128;

    // ldmatrix lane->element maps
    const int a_row = lane & 15;
    const int a_col = (lane >> 4) << 3;
    const int b_row = ((lane >> 4) << 3) + (lane & 7);
    const int b_col = ((lane >> 3) & 1) << 3;

    // global-load: row lr = t>>1, 4 chunks of 16B starting at (t&1)*32 halves
    const int lr = t >> 1;
    const int sg = (t & 1) * 32;

    const __half* Ar = A + (size_t)(n0 + lr) * K + sg;
    const __half* Br = B + (size_t)(m0 + lr) * K + sg;

    float acc[4][4][4];
    #pragma unroll
    for (int i = 0; i < 4; i++)
        #pragma unroll
        for (int j = 0; j < 4; j++)
            #pragma unroll
            for (int c = 0; c < 4; c++) acc[i][j][c] = 0.f;

    const int nK = K / 64;

    // prologue: stage 0
    {
        __half* As = Ash;  __half* Bs = Bsh;
        #pragma unroll
        for (int c = 0; c < 4; c++) {
            CP_ASYNC16(smem_u32(&As[lr * GLDSH + sg + c * 8]), Ar + c * 8);
            CP_ASYNC16(smem_u32(&Bs[lr * GLDSH + sg + c * 8]), Br + c * 8);
        }
        CP_COMMIT();
    }

    for (int kt = 0; kt < nK; kt++) {
        const int cur = kt & 1;
        if (kt + 1 < nK) {
            const int nxt = cur ^ 1;
            const int ko = (kt + 1) * 64;
            __half* As = Ash + nxt * G_STG;
            __half* Bs = Bsh + nxt * G_STG;
            #pragma unroll
            for (int c = 0; c < 4; c++) {
                CP_ASYNC16(smem_u32(&As[lr * GLDSH + sg + c * 8]), Ar + ko + c * 8);
                CP_ASYNC16(smem_u32(&Bs[lr * GLDSH + sg + c * 8]), Br + ko + c * 8);
            }
            CP_COMMIT();
            CP_WAIT(1);
        } else {
            CP_WAIT(0);
        }
        __syncthreads();

        const __half* As = Ash + cur * G_STG;
        const __half* Bs = Bsh + cur * G_STG;

        #pragma unroll
        for (int ks = 0; ks < 4; ks++) {
            const int kc = ks * 16;
            uint32_t af[4][4];
            #pragma unroll
            for (int mt = 0; mt < 4; mt++) {
                const int r = wm * 64 + mt * 16;
                LDMX4(af[mt][0], af[mt][1], af[mt][2], af[mt][3],
                      smem_u32(&As[(r + a_row) * GLDSH + kc + a_col]));
            }
            uint32_t bf[4][2];
            #pragma unroll
            for (int p = 0; p < 2; p++) {
                const int c = wn * 32 + p * 16;
                uint32_t r0, r1, r2, r3;
                LDMX4(r0, r1, r2, r3,
                      smem_u32(&Bs[(c + b_row) * GLDSH + kc + b_col]));
                bf[2*p][0] = r0;  bf[2*p][1] = r1;
                bf[2*p+1][0] = r2; bf[2*p+1][1] = r3;
            }
            #pragma unroll
            for (int mt = 0; mt < 4; mt++)
                #pragma unroll
                for (int nt = 0; nt < 4; nt++)
                    MMA_F16(acc[mt][nt], af[mt], bf[nt]);
        }
        __syncthreads();
    }

    #pragma unroll
    for (int mt = 0; mt < 4; mt++) {
        const int r0 = n0 + wm * 64 + mt * 16 + g;
        #pragma unroll
        for (int nt = 0; nt < 4; nt++) {
            const int col = m0 + wn * 32 + nt * 8 + 2 * tig;
            float2 v0 = make_float2(acc[mt][nt][0], acc[mt][nt][1]);
            float2 v1 = make_float2(acc[mt][nt][2], acc[mt][nt][3]);
            if (EPI == 1 || EPI == 3) {
                float2 bb = *(const float2*)&bias[col];
                v0.x += bb.x; v0.y += bb.y;
                v1.x += bb.x; v1.y += bb.y;
            }
            if (EPI == 3) {
                v0.x = fmaxf(v0.x, 0.f); v0.y = fmaxf(v0.y, 0.f);
                v1.x = fmaxf(v1.x, 0.f); v1.y = fmaxf(v1.y, 0.f);
            }
            if (EPI == 2 || EPI == 3) {
                float2 r0v = *(const float2*)&res[(size_t)r0 * M + col];
                float2 r1v = *(const float2*)&res[(size_t)(r0 + 8) * M + col];
                v0.x += r0v.x; v0.y += r0v.y;
                v1.x += r1v.x; v1.y += r1v.y;
            }
            if (HOUT) {
                __half* C = (__half*)Cv;
                *(__half2*)&C[(size_t)r0 * M + col]       = __floats2half2_rn(v0.x, v0.y);
                *(__half2*)&C[(size_t)(r0 + 8) * M + col] = __floats2half2_rn(v1.x, v1.y);
            } else {
                float* C = (float*)Cv;
                *(float2*)&C[(size_t)r0 * M + col]       = v0;
                *(float2*)&C[(size_t)(r0 + 8) * M + col] = v1;
            }
        }
    }
}

// ---------------- FP16 tensor-core flash attention (round-7, proven) --------
#define HQS  0
#define HKS  9216
#define HVS  18432
#define HPS  27648
#define HTOT 36864
#define AMSK_B (HTOT*2)
#define ASMEM_BYTES (AMSK_B + 2*64*4)
#define KSTG 4608

__global__ __launch_bounds__(256) void attn_tc(const __half* __restrict__ QKV,
                                               const unsigned char* __restrict__ mask,
                                               __half* __restrict__ O)
{
    extern __shared__ char shb[];
    __half* Qs  = (__half*)shb + HQS;
    __half* Ks  = (__half*)shb + HKS;
    __half* Vs  = (__half*)shb + HVS;
    __half* Ps  = (__half*)shb + HPS;
    float*  msk = (float*)(shb + AMSK_B);

    const int t    = threadIdx.x;
    const int lane = t & 31;
    const int warp = t >> 5;
    const int g    = lane >> 2;
    const int tig  = lane & 3;
    const int q0   = blockIdx.x * 128;
    const int h    = blockIdx.y;
    const int b    = blockIdx.z;
    const size_t baseQ = (size_t)b * SEQ * D3 + (size_t)h * DKH;
    const size_t baseK = baseQ + D_MODEL;
    const size_t baseV = baseQ + 2 * D_MODEL;
    const size_t baseO = (size_t)b * SEQ * D_MODEL + (size_t)h * DKH;
    const int rA = warp * 16 + g;

    const int a_row = lane & 15;
    const int a_col = (lane >> 4) << 3;
    const int b_row = ((lane >> 4) << 3) + (lane & 7);
    const int b_col = ((lane >> 3) & 1) << 3;

    #pragma unroll
    for (int i = 0; i < 4; i++) {
        int idx = t + i * 256, row = idx >> 3, s8 = (idx & 7) * 8;
        CP_ASYNC16(smem_u32(&Qs[row * 72 + s8]),
                   &QKV[baseQ + (size_t)(q0 + row) * D3 + s8]);
    }
    #pragma unroll
    for (int i = 0; i < 2; i++) {
        int idx = t + i * 256, row = idx >> 3, s8 = (idx & 7) * 8;
        CP_ASYNC16(smem_u32(&Ks[row * 72 + s8]),
                   &QKV[baseK + (size_t)row * D3 + s8]);
        CP_ASYNC16(smem_u32(&Vs[row * 72 + s8]),
                   &QKV[baseV + (size_t)row * D3 + s8]);
    }
    if (t < 64) msk[t] = mask[(size_t)b * SEQ + t] ? -3.0e38f : 0.f;
    CP_COMMIT();
    CP_WAIT(0);
    __syncthreads();

    uint32_t qf[4][4];
    #pragma unroll
    for (int kc4 = 0; kc4 < 4; kc4++) {
        LDMX4(qf[kc4][0], qf[kc4][1], qf[kc4][2], qf[kc4][3],
              smem_u32(&Qs[(warp * 16 + a_row) * 72 + kc4 * 16 + a_col]));
    }

    float m0 = -3.0e38f, m1 = -3.0e38f, l0 = 0.f, l1 = 0.f;
    float oacc[8][4];
    #pragma unroll
    for (int nt = 0; nt < 8; nt++)
        #pragma unroll
        for (int c = 0; c < 4; c++) oacc[nt][c] = 0.f;

    const int ntiles = SEQ / 64;
    for (int kt = 0; kt < ntiles; kt++) {
        const int cur = kt & 1;
        const bool pref = (kt + 1 < ntiles);
        if (pref) {
            const int nxt = cur ^ 1;
            const int k0n = (kt + 1) * 64;
            #pragma unroll
            for (int i = 0; i < 2; i++) {
                int idx = t + i * 256, row = idx >> 3, s8 = (idx & 7) * 8;
                CP_ASYNC16(smem_u32(&Ks[nxt * KSTG + row * 72 + s8]),
                           &QKV[baseK + (size_t)(k0n + row) * D3 + s8]);
                CP_ASYNC16(smem_u32(&Vs[nxt * KSTG + row * 72 + s8]),
                           &QKV[baseV + (size_t)(k0n + row) * D3 + s8]);
            }
            if (t < 64) msk[nxt * 64 + t] =
                mask[(size_t)b * SEQ + k0n + t] ? -3.0e38f : 0.f;
            CP_COMMIT();
        }
        const __half* Kc = Ks + cur * KSTG;
        const __half* Vc = Vs + cur * KSTG;
        const float*  mc = msk + cur * 64;

        float sc[8][4];
        #pragma unroll
        for (int nt = 0; nt < 8; nt++)
            #pragma unroll
            for (int c = 0; c < 4; c++) sc[nt][c] = 0.f;

        #pragma unroll
        for (int kc4 = 0; kc4 < 4; kc4++) {
            const int kc = kc4 * 16;
            #pragma unroll
            for (int p = 0; p < 4; p++) {
                const int c = p * 16;
                uint32_t r0, r1, r2, r3;
                LDMX4(r0, r1, r2, r3,
                      smem_u32(&Kc[(c + b_row) * 72 + kc + b_col]));
                uint32_t b0[2] = {r0, r1};
                uint32_t b1[2] = {r2, r3};
                MMA_F16(sc[2*p],     qf[kc4], b0);
                MMA_F16(sc[2*p + 1], qf[kc4], b1);
            }
        }

        float tm0 = -3.0e38f, tm1 = -3.0e38f;
        #pragma unroll
        for (int nt = 0; nt < 8; nt++) {
            const float mk0 = mc[nt * 8 + 2 * tig];
            const float mk1 = mc[nt * 8 + 2 * tig + 1];
            sc[nt][0] = sc[nt][0] * 0.125f + mk0;
            sc[nt][1] = sc[nt][1] * 0.125f + mk1;
            sc[nt][2] = sc[nt][2] * 0.125f + mk0;
            sc[nt][3] = sc[nt][3] * 0.125f + mk1;
            tm0 = fmaxf(tm0, fmaxf(sc[nt][0], sc[nt][1]));
            tm1 = fmaxf(tm1, fmaxf(sc[nt][2], sc[nt][3]));
        }
        tm0 = fmaxf(tm0, __shfl_xor_sync(0xffffffffu, tm0, 1));
        tm0 = fmaxf(tm0, __shfl_xor_sync(0xffffffffu, tm0, 2));
        tm1 = fmaxf(tm1, __shfl_xor_sync(0xffffffffu, tm1, 1));
        tm1 = fmaxf(tm1, __shfl_xor_sync(0xffffffffu, tm1, 2));

        const float nm0 = fmaxf(m0, tm0), nm1 = fmaxf(m1, tm1);
        const float a0 = __expf(m0 - nm0), a1 = __expf(m1 - nm1);

        float ps0 = 0.f, ps1 = 0.f;
        #pragma unroll
        for (int nt = 0; nt < 8; nt++) {
            const float p0 = __expf(sc[nt][0] - nm0);
            const float p1 = __expf(sc[nt][1] - nm0);
            const float p2 = __expf(sc[nt][2] - nm1);
            const float p3 = __expf(sc[nt][3] - nm1);
            ps0 += p0 + p1; ps1 += p2 + p3;
            *(__half2*)&Ps[rA * 72 + nt * 8 + 2*tig]       = __floats2half2_rn(p0, p1);
            *(__half2*)&Ps[(rA + 8) * 72 + nt * 8 + 2*tig] = __floats2half2_rn(p2, p3);
        }
        ps0 += __shfl_xor_sync(0xffffffffu, ps0, 1);
        ps0 += __shfl_xor_sync(0xffffffffu, ps0, 2);
        ps1 += __shfl_xor_sync(0xffffffffu, ps1, 1);
        ps1 += __shfl_xor_sync(0xffffffffu, ps1, 2);

        l0 = l0 * a0 + ps0;  l1 = l1 * a1 + ps1;
        m0 = nm0;  m1 = nm1;
        #pragma unroll
        for (int nt = 0; nt < 8; nt++) {
            oacc[nt][0] *= a0; oacc[nt][1] *= a0;
            oacc[nt][2] *= a1; oacc[nt][3] *= a1;
        }
        __syncwarp();

        const int mi = lane >> 3, rr = lane & 7;
        #pragma unroll
        for (int kc4 = 0; kc4 < 4; kc4++) {
            const int kc = kc4 * 16;
            uint32_t af[4];
            LDMX4(af[0], af[1], af[2], af[3],
                  smem_u32(&Ps[(warp * 16 + a_row) * 72 + kc + a_col]));
            #pragma unroll
            for (int ntp = 0; ntp < 4; ntp++) {
                const int key = kc + ((mi & 1) << 3) + rr;
                const int dim = ntp * 16 + ((mi >> 1) << 3);
                uint32_t r0, r1, r2, r3;
                LDMX4_TRANS(r0, r1, r2, r3, smem_u32(&Vc[key * 72 + dim]));
                uint32_t b0[2] = {r0, r1};
                uint32_t b1[2] = {r2, r3};
                MMA_F16(oacc[2*ntp],     af, b0);
                MMA_F16(oacc[2*ntp + 1], af, b1);
            }
        }

        if (pref) CP_WAIT(0);
        __syncthreads();
    }

    const float i0 = 1.f / l0, i1 = 1.f / l1;
    #pragma unroll
    for (int nt = 0; nt < 8; nt++) {
        const int col = nt * 8 + 2 * tig;
        *(__half2*)&O[baseO + (size_t)(q0 + rA) * D_MODEL + col] =
            __floats2half2_rn(oacc[nt][0] * i0, oacc[nt][1] * i0);
        *(__half2*)&O[baseO + (size_t)(q0 + rA + 8) * D_MODEL + col] =
            __floats2half2_rn(oacc[nt][2] * i1, oacc[nt][3] * i1);
    }
}

// ---------------- launch ---------------------------------------------------
extern "C" void kernel_launch(void* const* d_in, const int* in_sizes, int n_in,
                              void* d_out, int out_size)
{
    const float* x     = (const float*)d_in[0];
    const unsigned char* mask = (const unsigned char*)d_in[1];
    const float* W_Q   = (const float*)d_in[2];
    const float* W_K   = (const float*)d_in[3];
    const float* W_V   = (const float*)d_in[4];
    const float* W_O   = (const float*)d_in[5];
    const float* W1    = (const float*)d_in[6];
    const float* b1    = (const float*)d_in[7];
    const float* W2    = (const float*)d_in[8];
    const float* b2    = (const float*)d_in[9];
    const float* g1    = (const float*)d_in[10];
    const float* beta1 = (const float*)d_in[11];
    const float* g2    = (const float*)d_in[12];
    const float* beta2 = (const float*)d_in[13];
    float* out = (float*)d_out;

    __half *h1, *qkv, *at, *h2, *f1;
    __half *wqkv, *wo, *w1, *w2;
    float *x1;
    cudaGetSymbolAddress((void**)&h1,   g_h1);
    cudaGetSymbolAddress((void**)&qkv,  g_qkv);
    cudaGetSymbolAddress((void**)&at,   g_at);
    cudaGetSymbolAddress((void**)&x1,   g_x1);
    cudaGetSymbolAddress((void**)&h2,   g_h2);
    cudaGetSymbolAddress((void**)&f1,   g_f1);
    cudaGetSymbolAddress((void**)&wqkv, g_wqkv);
    cudaGetSymbolAddress((void**)&wo,   g_wo);
    cudaGetSymbolAddress((void**)&w1,   g_w1);
    cudaGetSymbolAddress((void**)&w2,   g_w2);

    cudaFuncSetAttribute(attn_tc, cudaFuncAttributeMaxDynamicSharedMemorySize,
                         ASMEM_BYTES);
    cudaFuncSetAttribute(gemm_f16<0,1>, cudaFuncAttributeMaxDynamicSharedMemorySize, G_SMEM);
    cudaFuncSetAttribute(gemm_f16<2,0>, cudaFuncAttributeMaxDynamicSharedMemorySize, G_SMEM);
    cudaFuncSetAttribute(gemm_f16<1,1>, cudaFuncAttributeMaxDynamicSharedMemorySize, G_SMEM);
    cudaFuncSetAttribute(gemm_f16<3,0>, cudaFuncAttributeMaxDynamicSharedMemorySize, G_SMEM);

    const dim3 gQKV(D3/128,      NTOK/128);  // (24, 32)
    const dim3 gDD (D_MODEL/128, NTOK/128);  // (8, 32)
    const dim3 gDF (D_FF/128,    NTOK/128);  // (32, 32)
    const int DD4 = D_MODEL*D_MODEL/4, DF4 = D_FF*D_MODEL/4;

    // 0. weights -> fp16
    conv_qkv <<<3*DD4/256, 256>>>((const float4*)W_Q, (const float4*)W_K,
                                  (const float4*)W_V, wqkv);
    conv_half<<<(DD4+255)/256, 256>>>((const float4*)W_O, wo, DD4);
    conv_half<<<(DF4+255)/256, 256>>>((const float4*)W1,  w1, DF4);
    conv_half<<<(DF4+255)/256, 256>>>((const float4*)W2,  w2, DF4);

    // 1. pre-LN
    ln_kernel<<<NTOK, 256>>>(x, g1, beta1, h1);
    // 2. fused QKV projection
    gemm_f16<0,1><<<gQKV, 256, G_SMEM>>>(h1, wqkv, qkv, NTOK, D3, D_MODEL, nullptr, nullptr);
    // 3. flash attention
    attn_tc<<<dim3(SEQ/128, HEADS, BATCH), 256, ASMEM_BYTES>>>(qkv, mask, at);
    // 4. output projection + residual (fp32 out)
    gemm_f16<2,0><<<gDD, 256, G_SMEM>>>(at, wo, x1, NTOK, D_MODEL, D_MODEL, nullptr, x);
    // 5. second LN
    ln_kernel<<<NTOK, 256>>>(x1, g2, beta2, h2);
    // 6. FFN1 (+b1)
    gemm_f16<1,1><<<gDF, 256, G_SMEM>>>(h2, w1, f1, NTOK, D_FF, D_MODEL, b1, nullptr);
    // 7. FFN2: relu(C + b2) + residual(x1), fp32 final
    gemm_f16<3,0><<<gDD, 256, G_SMEM>>>(f1, w2, out, NTOK, D_MODEL, D_FF, b2, x1);
}

// round 13
// speedup vs baseline: 1.1373x; 1.0638x over previous
#include <cuda_runtime.h>
#include <cuda_fp16.h>
#include <cstdint>
#include <cstddef>

#define D_MODEL 1024
#define D_FF    4096
#define HEADS   16
#define DKH     64
#define BATCH   2
#define SEQ     2048
#define NTOK    (BATCH*SEQ)
#define D3      (3*D_MODEL)

// ---------------- scratch (device globals; no allocations allowed) ----------
__device__ __half g_h1 [NTOK * D_MODEL];
__device__ __half g_qkv[NTOK * D3];
__device__ __half g_at [NTOK * D_MODEL];
__device__ float  g_x1 [NTOK * D_MODEL];
__device__ __half g_h2 [NTOK * D_MODEL];
__device__ __half g_f1 [NTOK * D_FF];
__device__ __half g_wqkv[D3 * D_MODEL];
__device__ __half g_wo[D_MODEL * D_MODEL];
__device__ __half g_w1[D_FF * D_MODEL];
__device__ __half g_w2[D_MODEL * D_FF];

// ---------------- helpers ---------------------------------------------------
__device__ __forceinline__ uint32_t smem_u32(const void* p) {
    return (uint32_t)__cvta_generic_to_shared(p);
}
#define CP_ASYNC16(dst, src) \
    asm volatile("cp.async.cg.shared.global [%0], [%1], 16;\n" :: "r"(dst), "l"(src))
#define CP_COMMIT() asm volatile("cp.async.commit_group;\n" ::: "memory")
#define CP_WAIT(n)  asm volatile("cp.async.wait_group %0;\n" :: "n"(n) : "memory")

#define MMA_F16(d, a, b) \
    asm volatile("mma.sync.aligned.m16n8k16.row.col.f32.f16.f16.f32 " \
                 "{%0,%1,%2,%3},{%4,%5,%6,%7},{%8,%9},{%0,%1,%2,%3};" \
                 : "+f"(d[0]), "+f"(d[1]), "+f"(d[2]), "+f"(d[3]) \
                 : "r"(a[0]), "r"(a[1]), "r"(a[2]), "r"(a[3]), \
                   "r"(b[0]), "r"(b[1]))

#define LDMX4(r0, r1, r2, r3, addr) \
    asm volatile("ldmatrix.sync.aligned.m8n8.x4.shared.b16 {%0,%1,%2,%3}, [%4];" \
                 : "=r"(r0), "=r"(r1), "=r"(r2), "=r"(r3) : "r"(addr))
#define LDMX4_TRANS(r0, r1, r2, r3, addr) \
    asm volatile("ldmatrix.sync.aligned.m8n8.x4.trans.shared.b16 {%0,%1,%2,%3}, [%4];" \
                 : "=r"(r0), "=r"(r1), "=r"(r2), "=r"(r3) : "r"(addr))

// ---------------- weight conversion -----------------------------------------
__global__ __launch_bounds__(256) void conv_qkv(const float4* __restrict__ q,
                                                const float4* __restrict__ k,
                                                const float4* __restrict__ v,
                                                __half* __restrict__ out)
{
    const int per = D_MODEL * D_MODEL / 4;
    int i = blockIdx.x * 256 + threadIdx.x;
    float4 val;
    if (i < per)            val = q[i];
    else if (i < 2 * per)   val = k[i - per];
    else                    val = v[i - 2 * per];
    __half2* o = (__half2*)(out + (size_t)i * 4);
    o[0] = __floats2half2_rn(val.x, val.y);
    o[1] = __floats2half2_rn(val.z, val.w);
}

// all remaining weights (W_O, W1, W2) in one launch
__global__ __launch_bounds__(256) void conv_rest(const float4* __restrict__ wo_in,
                                                 const float4* __restrict__ w1_in,
                                                 const float4* __restrict__ w2_in,
                                                 __half* __restrict__ wo_out,
                                                 __half* __restrict__ w1_out,
                                                 __half* __restrict__ w2_out)
{
    const int nDD = D_MODEL * D_MODEL / 4;
    const int nDF = D_FF * D_MODEL / 4;
    int i = blockIdx.x * 256 + threadIdx.x;
    const float4* src; __half* dst; int j;
    if (i < nDD)             { src = wo_in; dst = wo_out; j = i; }
    else if (i < nDD + nDF)  { src = w1_in; dst = w1_out; j = i - nDD; }
    else if (i < nDD + 2*nDF){ src = w2_in; dst = w2_out; j = i - nDD - nDF; }
    else return;
    float4 v = src[j];
    __half2* o = (__half2*)(dst + (size_t)j * 4);
    o[0] = __floats2half2_rn(v.x, v.y);
    o[1] = __floats2half2_rn(v.z, v.w);
}

// ---------------- LayerNorm (single-pass: sum + sumsq together) -------------
__global__ __launch_bounds__(256) void ln_kernel(const float* __restrict__ x,
                                                 const float* __restrict__ g,
                                                 const float* __restrict__ b,
                                                 __half* __restrict__ out)
{
    __shared__ float redS[8], redQ[8];
    __shared__ float bmu, brs;
    const int row = blockIdx.x;
    const int t = threadIdx.x;
    const int lane = t & 31, w = t >> 5;

    const float4* x4 = (const float4*)x + (size_t)row * 256;
    float4 v = x4[t];

    float s  = v.x + v.y + v.z + v.w;
    float s2 = v.x*v.x + v.y*v.y + v.z*v.z + v.w*v.w;
    #pragma unroll
    for (int o = 16; o; o >>= 1) {
        s  += __shfl_xor_sync(0xffffffffu, s, o);
        s2 += __shfl_xor_sync(0xffffffffu, s2, o);
    }
    if (lane == 0) { redS[w] = s; redQ[w] = s2; }
    __syncthreads();
    if (t == 0) {
        float ts = 0.f, tq = 0.f;
        #pragma unroll
        for (int i = 0; i < 8; i++) { ts += redS[i]; tq += redQ[i]; }
        const float mu = ts * (1.f / 1024.f);
        const float var = tq * (1.f / 1024.f) - mu * mu;
        bmu = mu;
        brs = rsqrtf(var + 1e-5f);
    }
    __syncthreads();
    const float mu = bmu, rs = brs;

    float4 gv = ((const float4*)g)[t];
    float4 bv = ((const float4*)b)[t];
    __half2* orow = (__half2*)(out + (size_t)row * 1024);
    orow[t*2]   = __floats2half2_rn((v.x - mu)*rs*gv.x + bv.x,
                                    (v.y - mu)*rs*gv.y + bv.y);
    orow[t*2+1] = __floats2half2_rn((v.z - mu)*rs*gv.z + bv.z,
                                    (v.w - mu)*rs*gv.w + bv.w);
}

// ---------------- FP16 tensor-core GEMM NT (round-7 shape, 3-stage ring) ----
// C[N,M] = A[N,K] * B[M,K]^T.  128x128 tile, BK=32, 256 thr, 2x4 warps,
// 64x32/warp via 4x4 m16n8k16.  cp.async 3-stage ring (2 tiles in flight),
// dynamic smem 60KB -> 2 CTA/SM, ldmatrix.x4 fragments.
// EPI: 0=none, 1=+bias, 2=+res, 3=relu(+bias)+res.  HOUT: 1 = store half.
#define GLDSH 40                     // 32 + 8 pad halves; 80B rows
#define G_STG (128*GLDSH)            // halves per stage per matrix
#define G_SMEM (6*G_STG*2)           // 3 stages x (A+B) = 61440 bytes

template<int EPI, int HOUT>
__global__ __launch_bounds__(256) void gemm_f16(const __half* __restrict__ A,
                                                const __half* __restrict__ B,
                                                void* __restrict__ Cv,
                                                int N, int M, int K,
                                                const float* __restrict__ bias,
                                                const float* __restrict__ res)
{
    extern __shared__ __align__(16) char sh[];
    __half* Ash = (__half*)sh;                // [3][128][40]
    __half* Bsh = (__half*)sh + 3 * G_STG;    // [3][128][40]

    const int t    = threadIdx.x;
    const int lane = t & 31;
    const int warp = t >> 5;
    const int wm   = warp >> 2;
    const int wn   = warp & 3;
    const int g    = lane >> 2;
    const int tig  = lane & 3;
    const int n0   = blockIdx.y * 128;
    const int m0   = blockIdx.x * 128;

    // ldmatrix lane->element maps
    const int a_row = lane & 15;
    const int a_col = (lane >> 4) << 3;
    const int b_row = ((lane >> 4) << 3) + (lane & 7);
    const int b_col = ((lane >> 3) & 1) << 3;

    const int lr = t >> 1;             // 0..127
    const int sg = (t & 1) * 16;       // 0 or 16 halves

    const __half* Ar = A + (size_t)(n0 + lr) * K + sg;
    const __half* Br = B + (size_t)(m0 + lr) * K + sg;

    float acc[4][4][4];
    #pragma unroll
    for (int i = 0; i < 4; i++)
        #pragma unroll
        for (int j = 0; j < 4; j++)
            #pragma unroll
            for (int c = 0; c < 4; c++) acc[i][j][c] = 0.f;

    const int nK = K / 32;

    // prologue: stages 0 and 1 (tiles 0, 1)
    #pragma unroll
    for (int p = 0; p < 2; p++) {
        __half* As = Ash + p * G_STG;
        __half* Bs = Bsh + p * G_STG;
        const int ko = p * 32;
        CP_ASYNC16(smem_u32(&As[lr * GLDSH + sg]),     Ar + ko);
        CP_ASYNC16(smem_u32(&As[lr * GLDSH + sg + 8]), Ar + ko + 8);
        CP_ASYNC16(smem_u32(&Bs[lr * GLDSH + sg]),     Br + ko);
        CP_ASYNC16(smem_u32(&Bs[lr * GLDSH + sg + 8]), Br + ko + 8);
        CP_COMMIT();
    }

    int cur = 0;
    for (int kt = 0; kt < nK; kt++) {
        // prefetch tile kt+2 into stage (cur+2)%3 (the stage read at kt-1)
        if (kt + 2 < nK) {
            int nxt = cur + 2; if (nxt >= 3) nxt -= 3;
            const int ko = (kt + 2) * 32;
            __half* As = Ash + nxt * G_STG;
            __half* Bs = Bsh + nxt * G_STG;
            CP_ASYNC16(smem_u32(&As[lr * GLDSH + sg]),     Ar + ko);
            CP_ASYNC16(smem_u32(&As[lr * GLDSH + sg + 8]), Ar + ko + 8);
            CP_ASYNC16(smem_u32(&Bs[lr * GLDSH + sg]),     Br + ko);
            CP_ASYNC16(smem_u32(&Bs[lr * GLDSH + sg + 8]), Br + ko + 8);
            CP_COMMIT();
        }
        const int rem = nK - 1 - kt;
        if (rem >= 2)      CP_WAIT(2);
        else if (rem == 1) CP_WAIT(1);
        else               CP_WAIT(0);
        __syncthreads();

        const __half* As = Ash + cur * G_STG;
        const __half* Bs = Bsh + cur * G_STG;

        #pragma unroll
        for (int ks = 0; ks < 2; ks++) {
            const int kc = ks * 16;
            uint32_t af[4][4];
            #pragma unroll
            for (int mt = 0; mt < 4; mt++) {
                const int r = wm * 64 + mt * 16;
                LDMX4(af[mt][0], af[mt][1], af[mt][2], af[mt][3],
                      smem_u32(&As[(r + a_row) * GLDSH + kc + a_col]));
            }
            uint32_t bf[4][2];
            #pragma unroll
            for (int p = 0; p < 2; p++) {
                const int c = wn * 32 + p * 16;
                uint32_t r0, r1, r2, r3;
                LDMX4(r0, r1, r2, r3,
                      smem_u32(&Bs[(c + b_row) * GLDSH + kc + b_col]));
                bf[2*p][0] = r0;  bf[2*p][1] = r1;
                bf[2*p+1][0] = r2; bf[2*p+1][1] = r3;
            }
            #pragma unroll
            for (int mt = 0; mt < 4; mt++)
                #pragma unroll
                for (int nt = 0; nt < 4; nt++)
                    MMA_F16(acc[mt][nt], af[mt], bf[nt]);
        }
        __syncthreads();
        if (++cur >= 3) cur = 0;
    }

    #pragma unroll
    for (int mt = 0; mt < 4; mt++) {
        const int r0 = n0 + wm * 64 + mt * 16 + g;
        #pragma unroll
        for (int nt = 0; nt < 4; nt++) {
            const int col = m0 + wn * 32 + nt * 8 + 2 * tig;
            float2 v0 = make_float2(acc[mt][nt][0], acc[mt][nt][1]);
            float2 v1 = make_float2(acc[mt][nt][2], acc[mt][nt][3]);
            if (EPI == 1 || EPI == 3) {
                float2 bb = *(const float2*)&bias[col];
                v0.x += bb.x; v0.y += bb.y;
                v1.x += bb.x; v1.y += bb.y;
            }
            if (EPI == 3) {
                v0.x = fmaxf(v0.x, 0.f); v0.y = fmaxf(v0.y, 0.f);
                v1.x = fmaxf(v1.x, 0.f); v1.y = fmaxf(v1.y, 0.f);
            }
            if (EPI == 2 || EPI == 3) {
                float2 r0v = *(const float2*)&res[(size_t)r0 * M + col];
                float2 r1v = *(const float2*)&res[(size_t)(r0 + 8) * M + col];
                v0.x += r0v.x; v0.y += r0v.y;
                v1.x += r1v.x; v1.y += r1v.y;
            }
            if (HOUT) {
                __half* C = (__half*)Cv;
                *(__half2*)&C[(size_t)r0 * M + col]       = __floats2half2_rn(v0.x, v0.y);
                *(__half2*)&C[(size_t)(r0 + 8) * M + col] = __floats2half2_rn(v1.x, v1.y);
            } else {
                float* C = (float*)Cv;
                *(float2*)&C[(size_t)r0 * M + col]       = v0;
                *(float2*)&C[(size_t)(r0 + 8) * M + col] = v1;
            }
        }
    }
}

// ---------------- FP16 tensor-core flash attention (round-7, proven) --------
#define HQS  0
#define HKS  9216
#define HVS  18432
#define HPS  27648
#define HTOT 36864
#define AMSK_B (HTOT*2)
#define ASMEM_BYTES (AMSK_B + 2*64*4)
#define KSTG 4608

__global__ __launch_bounds__(256) void attn_tc(const __half* __restrict__ QKV,
                                               const unsigned char* __restrict__ mask,
                                               __half* __restrict__ O)
{
    extern __shared__ char shb[];
    __half* Qs  = (__half*)shb + HQS;
    __half* Ks  = (__half*)shb + HKS;
    __half* Vs  = (__half*)shb + HVS;
    __half* Ps  = (__half*)shb + HPS;
    float*  msk = (float*)(shb + AMSK_B);

    const int t    = threadIdx.x;
    const int lane = t & 31;
    const int warp = t >> 5;
    const int g    = lane >> 2;
    const int tig  = lane & 3;
    const int q0   = blockIdx.x * 128;
    const int h    = blockIdx.y;
    const int b    = blockIdx.z;
    const size_t baseQ = (size_t)b * SEQ * D3 + (size_t)h * DKH;
    const size_t baseK = baseQ + D_MODEL;
    const size_t baseV = baseQ + 2 * D_MODEL;
    const size_t baseO = (size_t)b * SEQ * D_MODEL + (size_t)h * DKH;
    const int rA = warp * 16 + g;

    const int a_row = lane & 15;
    const int a_col = (lane >> 4) << 3;
    const int b_row = ((lane >> 4) << 3) + (lane & 7);
    const int b_col = ((lane >> 3) & 1) << 3;

    #pragma unroll
    for (int i = 0; i < 4; i++) {
        int idx = t + i * 256, row = idx >> 3, s8 = (idx & 7) * 8;
        CP_ASYNC16(smem_u32(&Qs[row * 72 + s8]),
                   &QKV[baseQ + (size_t)(q0 + row) * D3 + s8]);
    }
    #pragma unroll
    for (int i = 0; i < 2; i++) {
        int idx = t + i * 256, row = idx >> 3, s8 = (idx & 7) * 8;
        CP_ASYNC16(smem_u32(&Ks[row * 72 + s8]),
                   &QKV[baseK + (size_t)row * D3 + s8]);
        CP_ASYNC16(smem_u32(&Vs[row * 72 + s8]),
                   &QKV[baseV + (size_t)row * D3 + s8]);
    }
    if (t < 64) msk[t] = mask[(size_t)b * SEQ + t] ? -3.0e38f : 0.f;
    CP_COMMIT();
    CP_WAIT(0);
    __syncthreads();

    uint32_t qf[4][4];
    #pragma unroll
    for (int kc4 = 0; kc4 < 4; kc4++) {
        LDMX4(qf[kc4][0], qf[kc4][1], qf[kc4][2], qf[kc4][3],
              smem_u32(&Qs[(warp * 16 + a_row) * 72 + kc4 * 16 + a_col]));
    }

    float m0 = -3.0e38f, m1 = -3.0e38f, l0 = 0.f, l1 = 0.f;
    float oacc[8][4];
    #pragma unroll
    for (int nt = 0; nt < 8; nt++)
        #pragma unroll
        for (int c = 0; c < 4; c++) oacc[nt][c] = 0.f;

    const int ntiles = SEQ / 64;
    for (int kt = 0; kt < ntiles; kt++) {
        const int cur = kt & 1;
        const bool pref = (kt + 1 < ntiles);
        if (pref) {
            const int nxt = cur ^ 1;
            const int k0n = (kt + 1) * 64;
            #pragma unroll
            for (int i = 0; i < 2; i++) {
                int idx = t + i * 256, row = idx >> 3, s8 = (idx & 7) * 8;
                CP_ASYNC16(smem_u32(&Ks[nxt * KSTG + row * 72 + s8]),
                           &QKV[baseK + (size_t)(k0n + row) * D3 + s8]);
                CP_ASYNC16(smem_u32(&Vs[nxt * KSTG + row * 72 + s8]),
                           &QKV[baseV + (size_t)(k0n + row) * D3 + s8]);
            }
            if (t < 64) msk[nxt * 64 + t] =
                mask[(size_t)b * SEQ + k0n + t] ? -3.0e38f : 0.f;
            CP_COMMIT();
        }
        const __half* Kc = Ks + cur * KSTG;
        const __half* Vc = Vs + cur * KSTG;
        const float*  mc = msk + cur * 64;

        float sc[8][4];
        #pragma unroll
        for (int nt = 0; nt < 8; nt++)
            #pragma unroll
            for (int c = 0; c < 4; c++) sc[nt][c] = 0.f;

        #pragma unroll
        for (int kc4 = 0; kc4 < 4; kc4++) {
            const int kc = kc4 * 16;
            #pragma unroll
            for (int p = 0; p < 4; p++) {
                const int c = p * 16;
                uint32_t r0, r1, r2, r3;
                LDMX4(r0, r1, r2, r3,
                      smem_u32(&Kc[(c + b_row) * 72 + kc + b_col]));
                uint32_t b0[2] = {r0, r1};
                uint32_t b1[2] = {r2, r3};
                MMA_F16(sc[2*p],     qf[kc4], b0);
                MMA_F16(sc[2*p + 1], qf[kc4], b1);
            }
        }

        float tm0 = -3.0e38f, tm1 = -3.0e38f;
        #pragma unroll
        for (int nt = 0; nt < 8; nt++) {
            const float mk0 = mc[nt * 8 + 2 * tig];
            const float mk1 = mc[nt * 8 + 2 * tig + 1];
            sc[nt][0] = sc[nt][0] * 0.125f + mk0;
            sc[nt][1] = sc[nt][1] * 0.125f + mk1;
            sc[nt][2] = sc[nt][2] * 0.125f + mk0;
            sc[nt][3] = sc[nt][3] * 0.125f + mk1;
            tm0 = fmaxf(tm0, fmaxf(sc[nt][0], sc[nt][1]));
            tm1 = fmaxf(tm1, fmaxf(sc[nt][2], sc[nt][3]));
        }
        tm0 = fmaxf(tm0, __shfl_xor_sync(0xffffffffu, tm0, 1));
        tm0 = fmaxf(tm0, __shfl_xor_sync(0xffffffffu, tm0, 2));
        tm1 = fmaxf(tm1, __shfl_xor_sync(0xffffffffu, tm1, 1));
        tm1 = fmaxf(tm1, __shfl_xor_sync(0xffffffffu, tm1, 2));

        const float nm0 = fmaxf(m0, tm0), nm1 = fmaxf(m1, tm1);
        const float a0 = __expf(m0 - nm0), a1 = __expf(m1 - nm1);

        float ps0 = 0.f, ps1 = 0.f;
        #pragma unroll
        for (int nt = 0; nt < 8; nt++) {
            const float p0 = __expf(sc[nt][0] - nm0);
            const float p1 = __expf(sc[nt][1] - nm0);
            const float p2 = __expf(sc[nt][2] - nm1);
            const float p3 = __expf(sc[nt][3] - nm1);
            ps0 += p0 + p1; ps1 += p2 + p3;
            *(__half2*)&Ps[rA * 72 + nt * 8 + 2*tig]       = __floats2half2_rn(p0, p1);
            *(__half2*)&Ps[(rA + 8) * 72 + nt * 8 + 2*tig] = __floats2half2_rn(p2, p3);
        }
        ps0 += __shfl_xor_sync(0xffffffffu, ps0, 1);
        ps0 += __shfl_xor_sync(0xffffffffu, ps0, 2);
        ps1 += __shfl_xor_sync(0xffffffffu, ps1, 1);
        ps1 += __shfl_xor_sync(0xffffffffu, ps1, 2);

        l0 = l0 * a0 + ps0;  l1 = l1 * a1 + ps1;
        m0 = nm0;  m1 = nm1;
        #pragma unroll
        for (int nt = 0; nt < 8; nt++) {
            oacc[nt][0] *= a0; oacc[nt][1] *= a0;
            oacc[nt][2] *= a1; oacc[nt][3] *= a1;
        }
        __syncwarp();

        const int mi = lane >> 3, rr = lane & 7;
        #pragma unroll
        for (int kc4 = 0; kc4 < 4; kc4++) {
            const int kc = kc4 * 16;
            uint32_t af[4];
            LDMX4(af[0], af[1], af[2], af[3],
                  smem_u32(&Ps[(warp * 16 + a_row) * 72 + kc + a_col]));
            #pragma unroll
            for (int ntp = 0; ntp < 4; ntp++) {
                const int key = kc + ((mi & 1) << 3) + rr;
                const int dim = ntp * 16 + ((mi >> 1) << 3);
                uint32_t r0, r1, r2, r3;
                LDMX4_TRANS(r0, r1, r2, r3, smem_u32(&Vc[key * 72 + dim]));
                uint32_t b0[2] = {r0, r1};
                uint32_t b1[2] = {r2, r3};
                MMA_F16(oacc[2*ntp],     af, b0);
                MMA_F16(oacc[2*ntp + 1], af, b1);
            }
        }

        if (pref) CP_WAIT(0);
        __syncthreads();
    }

    const float i0 = 1.f / l0, i1 = 1.f / l1;
    #pragma unroll
    for (int nt = 0; nt < 8; nt++) {
        const int col = nt * 8 + 2 * tig;
        *(__half2*)&O[baseO + (size_t)(q0 + rA) * D_MODEL + col] =
            __floats2half2_rn(oacc[nt][0] * i0, oacc[nt][1] * i0);
        *(__half2*)&O[baseO + (size_t)(q0 + rA + 8) * D_MODEL + col] =
            __floats2half2_rn(oacc[nt][2] * i1, oacc[nt][3] * i1);
    }
}

// ---------------- launch ---------------------------------------------------
extern "C" void kernel_launch(void* const* d_in, const int* in_sizes, int n_in,
                              void* d_out, int out_size)
{
    const float* x     = (const float*)d_in[0];
    const unsigned char* mask = (const unsigned char*)d_in[1];
    const float* W_Q   = (const float*)d_in[2];
    const float* W_K   = (const float*)d_in[3];
    const float* W_V   = (const float*)d_in[4];
    const float* W_O   = (const float*)d_in[5];
    const float* W1    = (const float*)d_in[6];
    const float* b1    = (const float*)d_in[7];
    const float* W2    = (const float*)d_in[8];
    const float* b2    = (const float*)d_in[9];
    const float* g1    = (const float*)d_in[10];
    const float* beta1 = (const float*)d_in[11];
    const float* g2    = (const float*)d_in[12];
    const float* beta2 = (const float*)d_in[13];
    float* out = (float*)d_out;

    __half *h1, *qkv, *at, *h2, *f1;
    __half *wqkv, *wo, *w1, *w2;
    float *x1;
    cudaGetSymbolAddress((void**)&h1,   g_h1);
    cudaGetSymbolAddress((void**)&qkv,  g_qkv);
    cudaGetSymbolAddress((void**)&at,   g_at);
    cudaGetSymbolAddress((void**)&x1,   g_x1);
    cudaGetSymbolAddress((void**)&h2,   g_h2);
    cudaGetSymbolAddress((void**)&f1,   g_f1);
    cudaGetSymbolAddress((void**)&wqkv, g_wqkv);
    cudaGetSymbolAddress((void**)&wo,   g_wo);
    cudaGetSymbolAddress((void**)&w1,   g_w1);
    cudaGetSymbolAddress((void**)&w2,   g_w2);

    cudaFuncSetAttribute(attn_tc, cudaFuncAttributeMaxDynamicSharedMemorySize,
                         ASMEM_BYTES);
    cudaFuncSetAttribute(gemm_f16<0,1>, cudaFuncAttributeMaxDynamicSharedMemorySize, G_SMEM);
    cudaFuncSetAttribute(gemm_f16<2,0>, cudaFuncAttributeMaxDynamicSharedMemorySize, G_SMEM);
    cudaFuncSetAttribute(gemm_f16<1,1>, cudaFuncAttributeMaxDynamicSharedMemorySize, G_SMEM);
    cudaFuncSetAttribute(gemm_f16<3,0>, cudaFuncAttributeMaxDynamicSharedMemorySize, G_SMEM);

    const dim3 gQKV(D3/128,      NTOK/128);  // (24, 32)
    const dim3 gDD (D_MODEL/128, NTOK/128);  // (8, 32)
    const dim3 gDF (D_FF/128,    NTOK/128);  // (32, 32)
    const int DD4 = D_MODEL*D_MODEL/4, DF4 = D_FF*D_MODEL/4;

    // 0. weights -> fp16 (2 launches)
    conv_qkv <<<3*DD4/256, 256>>>((const float4*)W_Q, (const float4*)W_K,
                                  (const float4*)W_V, wqkv);
    conv_rest<<<(DD4 + 2*DF4 + 255)/256, 256>>>((const float4*)W_O,
                                                (const float4*)W1,
                                                (const float4*)W2,
                                                wo, w1, w2);

    // 1. pre-LN
    ln_kernel<<<NTOK, 256>>>(x, g1, beta1, h1);
    // 2. fused QKV projection
    gemm_f16<0,1><<<gQKV, 256, G_SMEM>>>(h1, wqkv, qkv, NTOK, D3, D_MODEL, nullptr, nullptr);
    // 3. flash attention
    attn_tc<<<dim3(SEQ/128, HEADS, BATCH), 256, ASMEM_BYTES>>>(qkv, mask, at);
    // 4. output projection + residual (fp32 out)
    gemm_f16<2,0><<<gDD, 256, G_SMEM>>>(at, wo, x1, NTOK, D_MODEL, D_MODEL, nullptr, x);
    // 5. second LN
    ln_kernel<<<NTOK, 256>>>(x1, g2, beta2, h2);
    // 6. FFN1 (+b1)
    gemm_f16<1,1><<<gDF, 256, G_SMEM>>>(h2, w1, f1, NTOK, D_FF, D_MODEL, b1, nullptr);
    // 7. FFN2: relu(C + b2) + residual(x1), fp32 final
    gemm_f16<3,0><<<gDD, 256, G_SMEM>>>(f1, w2, out, NTOK, D_MODEL, D_FF, b2, x1);
}

// round 14
// speedup vs baseline: 1.1998x; 1.0549x over previous
#include <cuda_runtime.h>
#include <cuda_fp16.h>
#include <cstdint>
#include <cstddef>

#define D_MODEL 1024
#define D_FF    4096
#define HEADS   16
#define DKH     64
#define BATCH   2
#define SEQ     2048
#define NTOK    (BATCH*SEQ)
#define D3      (3*D_MODEL)

// ---------------- scratch (device globals; no allocations allowed) ----------
__device__ __half g_h1 [NTOK * D_MODEL];
__device__ __half g_qkv[NTOK * D3];
__device__ __half g_at [NTOK * D_MODEL];
__device__ float  g_x1 [NTOK * D_MODEL];
__device__ __half g_h2 [NTOK * D_MODEL];
__device__ __half g_f1 [NTOK * D_FF];
__device__ __half g_wqkv[D3 * D_MODEL];
__device__ __half g_wo[D_MODEL * D_MODEL];
__device__ __half g_w1[D_FF * D_MODEL];
__device__ __half g_w2[D_MODEL * D_FF];

// ---------------- helpers ---------------------------------------------------
__device__ __forceinline__ uint32_t smem_u32(const void* p) {
    return (uint32_t)__cvta_generic_to_shared(p);
}
#define CP_ASYNC16(dst, src) \
    asm volatile("cp.async.cg.shared.global [%0], [%1], 16;\n" :: "r"(dst), "l"(src))
#define CP_COMMIT() asm volatile("cp.async.commit_group;\n" ::: "memory")
#define CP_WAIT(n)  asm volatile("cp.async.wait_group %0;\n" :: "n"(n) : "memory")

#define MMA_F16(d, a, b) \
    asm volatile("mma.sync.aligned.m16n8k16.row.col.f32.f16.f16.f32 " \
                 "{%0,%1,%2,%3},{%4,%5,%6,%7},{%8,%9},{%0,%1,%2,%3};" \
                 : "+f"(d[0]), "+f"(d[1]), "+f"(d[2]), "+f"(d[3]) \
                 : "r"(a[0]), "r"(a[1]), "r"(a[2]), "r"(a[3]), \
                   "r"(b[0]), "r"(b[1]))

#define LDMX4(r0, r1, r2, r3, addr) \
    asm volatile("ldmatrix.sync.aligned.m8n8.x4.shared.b16 {%0,%1,%2,%3}, [%4];" \
                 : "=r"(r0), "=r"(r1), "=r"(r2), "=r"(r3) : "r"(addr))
#define LDMX4_TRANS(r0, r1, r2, r3, addr) \
    asm volatile("ldmatrix.sync.aligned.m8n8.x4.trans.shared.b16 {%0,%1,%2,%3}, [%4];" \
                 : "=r"(r0), "=r"(r1), "=r"(r2), "=r"(r3) : "r"(addr))

// ---------------- weight conversion -----------------------------------------
__global__ __launch_bounds__(256) void conv_qkv(const float4* __restrict__ q,
                                                const float4* __restrict__ k,
                                                const float4* __restrict__ v,
                                                __half* __restrict__ out)
{
    const int per = D_MODEL * D_MODEL / 4;
    int i = blockIdx.x * 256 + threadIdx.x;
    float4 val;
    if (i < per)            val = q[i];
    else if (i < 2 * per)   val = k[i - per];
    else                    val = v[i - 2 * per];
    __half2* o = (__half2*)(out + (size_t)i * 4);
    o[0] = __floats2half2_rn(val.x, val.y);
    o[1] = __floats2half2_rn(val.z, val.w);
}

__global__ __launch_bounds__(256) void conv_rest(const float4* __restrict__ wo_in,
                                                 const float4* __restrict__ w1_in,
                                                 const float4* __restrict__ w2_in,
                                                 __half* __restrict__ wo_out,
                                                 __half* __restrict__ w1_out,
                                                 __half* __restrict__ w2_out)
{
    const int nDD = D_MODEL * D_MODEL / 4;
    const int nDF = D_FF * D_MODEL / 4;
    int i = blockIdx.x * 256 + threadIdx.x;
    const float4* src; __half* dst; int j;
    if (i < nDD)             { src = wo_in; dst = wo_out; j = i; }
    else if (i < nDD + nDF)  { src = w1_in; dst = w1_out; j = i - nDD; }
    else if (i < nDD + 2*nDF){ src = w2_in; dst = w2_out; j = i - nDD - nDF; }
    else return;
    float4 v = src[j];
    __half2* o = (__half2*)(dst + (size_t)j * 4);
    o[0] = __floats2half2_rn(v.x, v.y);
    o[1] = __floats2half2_rn(v.z, v.w);
}

// ---------------- LayerNorm (single-pass) ------------------------------------
__global__ __launch_bounds__(256) void ln_kernel(const float* __restrict__ x,
                                                 const float* __restrict__ g,
                                                 const float* __restrict__ b,
                                                 __half* __restrict__ out)
{
    __shared__ float redS[8], redQ[8];
    __shared__ float bmu, brs;
    const int row = blockIdx.x;
    const int t = threadIdx.x;
    const int lane = t & 31, w = t >> 5;

    const float4* x4 = (const float4*)x + (size_t)row * 256;
    float4 v = x4[t];

    float s  = v.x + v.y + v.z + v.w;
    float s2 = v.x*v.x + v.y*v.y + v.z*v.z + v.w*v.w;
    #pragma unroll
    for (int o = 16; o; o >>= 1) {
        s  += __shfl_xor_sync(0xffffffffu, s, o);
        s2 += __shfl_xor_sync(0xffffffffu, s2, o);
    }
    if (lane == 0) { redS[w] = s; redQ[w] = s2; }
    __syncthreads();
    if (t == 0) {
        float ts = 0.f, tq = 0.f;
        #pragma unroll
        for (int i = 0; i < 8; i++) { ts += redS[i]; tq += redQ[i]; }
        const float mu = ts * (1.f / 1024.f);
        const float var = tq * (1.f / 1024.f) - mu * mu;
        bmu = mu;
        brs = rsqrtf(var + 1e-5f);
    }
    __syncthreads();
    const float mu = bmu, rs = brs;

    float4 gv = ((const float4*)g)[t];
    float4 bv = ((const float4*)b)[t];
    __half2* orow = (__half2*)(out + (size_t)row * 1024);
    orow[t*2]   = __floats2half2_rn((v.x - mu)*rs*gv.x + bv.x,
                                    (v.y - mu)*rs*gv.y + bv.y);
    orow[t*2+1] = __floats2half2_rn((v.z - mu)*rs*gv.z + bv.z,
                                    (v.w - mu)*rs*gv.w + bv.w);
}

// ---------------- FP16 tensor-core GEMM NT (64x128 tile, high occupancy) ----
// C[N,M] = A[N,K] * B[M,K]^T.  CTA: 64 token rows x 128 feature cols, BK=32.
// 8 warps in 2x4 grid, warp tile 32x32 (2x4 m16n8k16 frags, acc=32 regs).
// 4-stage cp.async ring, ONE __syncthreads per k-tile (prefetch after barrier
// targets the stage read at kt-1, ordered by the barrier).  launch_bounds
// (256,3) caps regs at 85 -> 3 CTA/SM (24 warps, ~37% occ).
// EPI: 0=none, 1=+bias, 2=+res, 3=relu(+bias)+res.  HOUT: 1 = store half.
#define GLDSH 40                     // 32 + 8 pad halves; 80B rows
#define G_ASTG (64*GLDSH)            // A stage halves
#define G_BSTG (128*GLDSH)           // B stage halves
#define G_NSTG 4
#define G_SMEM (G_NSTG*(G_ASTG+G_BSTG)*2)    // 61440 bytes

template<int EPI, int HOUT>
__global__ __launch_bounds__(256, 3) void gemm_f16(const __half* __restrict__ A,
                                                   const __half* __restrict__ B,
                                                   void* __restrict__ Cv,
                                                   int N, int M, int K,
                                                   const float* __restrict__ bias,
                                                   const float* __restrict__ res)
{
    extern __shared__ __align__(16) char sh[];
    __half* Ash = (__half*)sh;                     // [4][64][40]
    __half* Bsh = (__half*)sh + G_NSTG * G_ASTG;   // [4][128][40]

    const int t    = threadIdx.x;
    const int lane = t & 31;
    const int warp = t >> 5;
    const int wm   = warp >> 2;          // 0..1  (32-row slice)
    const int wn   = warp & 3;           // 0..3  (32-col slice)
    const int g    = lane >> 2;
    const int tig  = lane & 3;
    const int n0   = blockIdx.y * 64;    // token rows
    const int m0   = blockIdx.x * 128;   // feature cols

    // ldmatrix lane->element maps
    const int a_row = lane & 15;
    const int a_col = (lane >> 4) << 3;
    const int b_row = ((lane >> 4) << 3) + (lane & 7);
    const int b_col = ((lane >> 3) & 1) << 3;

    // global loads: A 1 chunk/thread (64 rows x 4 chunks), B 2 chunks/thread
    const int alr = t >> 2;              // 0..63
    const int ach = (t & 3) * 8;         // 0,8,16,24 halves
    const __half* Arp  = A + (size_t)(n0 + alr) * K + ach;
    const __half* Brp0 = B + (size_t)(m0 + alr) * K + ach;        // rows 0..63
    const __half* Brp1 = B + (size_t)(m0 + alr + 64) * K + ach;   // rows 64..127

    float acc[2][4][4];
    #pragma unroll
    for (int i = 0; i < 2; i++)
        #pragma unroll
        for (int j = 0; j < 4; j++)
            #pragma unroll
            for (int c = 0; c < 4; c++) acc[i][j][c] = 0.f;

    const int nK = K / 32;

    // prologue: tiles 0..2 into stages 0..2
    #pragma unroll
    for (int p = 0; p < 3; p++) {
        __half* As = Ash + p * G_ASTG;
        __half* Bs = Bsh + p * G_BSTG;
        const int ko = p * 32;
        CP_ASYNC16(smem_u32(&As[alr * GLDSH + ach]),        Arp + ko);
        CP_ASYNC16(smem_u32(&Bs[alr * GLDSH + ach]),        Brp0 + ko);
        CP_ASYNC16(smem_u32(&Bs[(alr + 64) * GLDSH + ach]), Brp1 + ko);
        CP_COMMIT();
    }

    for (int kt = 0; kt < nK; kt++) {
        const int rem = nK - 1 - kt;
        if (rem >= 2)      CP_WAIT(2);
        else if (rem == 1) CP_WAIT(1);
        else               CP_WAIT(0);
        __syncthreads();   // tile kt visible to all; also orders stage reuse

        // prefetch tile kt+3 into stage (kt+3)&3 (read at kt-1; safe post-barrier)
        if (kt + 3 < nK) {
            const int p = (kt + 3) & 3;
            const int ko = (kt + 3) * 32;
            __half* As = Ash + p * G_ASTG;
            __half* Bs = Bsh + p * G_BSTG;
            CP_ASYNC16(smem_u32(&As[alr * GLDSH + ach]),        Arp + ko);
            CP_ASYNC16(smem_u32(&Bs[alr * GLDSH + ach]),        Brp0 + ko);
            CP_ASYNC16(smem_u32(&Bs[(alr + 64) * GLDSH + ach]), Brp1 + ko);
            CP_COMMIT();
        }

        const __half* As = Ash + (kt & 3) * G_ASTG;
        const __half* Bs = Bsh + (kt & 3) * G_BSTG;

        #pragma unroll
        for (int ks = 0; ks < 2; ks++) {
            const int kc = ks * 16;
            uint32_t af[2][4];
            #pragma unroll
            for (int mt = 0; mt < 2; mt++) {
                const int r = wm * 32 + mt * 16;
                LDMX4(af[mt][0], af[mt][1], af[mt][2], af[mt][3],
                      smem_u32(&As[(r + a_row) * GLDSH + kc + a_col]));
            }
            uint32_t bf[4][2];
            #pragma unroll
            for (int p = 0; p < 2; p++) {
                const int c = wn * 32 + p * 16;
                uint32_t r0, r1, r2, r3;
                LDMX4(r0, r1, r2, r3,
                      smem_u32(&Bs[(c + b_row) * GLDSH + kc + b_col]));
                bf[2*p][0] = r0;  bf[2*p][1] = r1;
                bf[2*p+1][0] = r2; bf[2*p+1][1] = r3;
            }
            #pragma unroll
            for (int mt = 0; mt < 2; mt++)
                #pragma unroll
                for (int nt = 0; nt < 4; nt++)
                    MMA_F16(acc[mt][nt], af[mt], bf[nt]);
        }
        // no trailing sync (4-stage ring; reuse ordered by next leading sync)
    }

    #pragma unroll
    for (int mt = 0; mt < 2; mt++) {
        const int r0 = n0 + wm * 32 + mt * 16 + g;
        #pragma unroll
        for (int nt = 0; nt < 4; nt++) {
            const int col = m0 + wn * 32 + nt * 8 + 2 * tig;
            float2 v0 = make_float2(acc[mt][nt][0], acc[mt][nt][1]);
            float2 v1 = make_float2(acc[mt][nt][2], acc[mt][nt][3]);
            if (EPI == 1 || EPI == 3) {
                float2 bb = *(const float2*)&bias[col];
                v0.x += bb.x; v0.y += bb.y;
                v1.x += bb.x; v1.y += bb.y;
            }
            if (EPI == 3) {
                v0.x = fmaxf(v0.x, 0.f); v0.y = fmaxf(v0.y, 0.f);
                v1.x = fmaxf(v1.x, 0.f); v1.y = fmaxf(v1.y, 0.f);
            }
            if (EPI == 2 || EPI == 3) {
                float2 r0v = *(const float2*)&res[(size_t)r0 * M + col];
                float2 r1v = *(const float2*)&res[(size_t)(r0 + 8) * M + col];
                v0.x += r0v.x; v0.y += r0v.y;
                v1.x += r1v.x; v1.y += r1v.y;
            }
            if (HOUT) {
                __half* C = (__half*)Cv;
                *(__half2*)&C[(size_t)r0 * M + col]       = __floats2half2_rn(v0.x, v0.y);
                *(__half2*)&C[(size_t)(r0 + 8) * M + col] = __floats2half2_rn(v1.x, v1.y);
            } else {
                float* C = (float*)Cv;
                *(float2*)&C[(size_t)r0 * M + col]       = v0;
                *(float2*)&C[(size_t)(r0 + 8) * M + col] = v1;
            }
        }
    }
}

// ---------------- FP16 tensor-core flash attention (round-7, proven) --------
#define HQS  0
#define HKS  9216
#define HVS  18432
#define HPS  27648
#define HTOT 36864
#define AMSK_B (HTOT*2)
#define ASMEM_BYTES (AMSK_B + 2*64*4)
#define KSTG 4608

__global__ __launch_bounds__(256) void attn_tc(const __half* __restrict__ QKV,
                                               const unsigned char* __restrict__ mask,
                                               __half* __restrict__ O)
{
    extern __shared__ char shb[];
    __half* Qs  = (__half*)shb + HQS;
    __half* Ks  = (__half*)shb + HKS;
    __half* Vs  = (__half*)shb + HVS;
    __half* Ps  = (__half*)shb + HPS;
    float*  msk = (float*)(shb + AMSK_B);

    const int t    = threadIdx.x;
    const int lane = t & 31;
    const int warp = t >> 5;
    const int g    = lane >> 2;
    const int tig  = lane & 3;
    const int q0   = blockIdx.x * 128;
    const int h    = blockIdx.y;
    const int b    = blockIdx.z;
    const size_t baseQ = (size_t)b * SEQ * D3 + (size_t)h * DKH;
    const size_t baseK = baseQ + D_MODEL;
    const size_t baseV = baseQ + 2 * D_MODEL;
    const size_t baseO = (size_t)b * SEQ * D_MODEL + (size_t)h * DKH;
    const int rA = warp * 16 + g;

    const int a_row = lane & 15;
    const int a_col = (lane >> 4) << 3;
    const int b_row = ((lane >> 4) << 3) + (lane & 7);
    const int b_col = ((lane >> 3) & 1) << 3;

    #pragma unroll
    for (int i = 0; i < 4; i++) {
        int idx = t + i * 256, row = idx >> 3, s8 = (idx & 7) * 8;
        CP_ASYNC16(smem_u32(&Qs[row * 72 + s8]),
                   &QKV[baseQ + (size_t)(q0 + row) * D3 + s8]);
    }
    #pragma unroll
    for (int i = 0; i < 2; i++) {
        int idx = t + i * 256, row = idx >> 3, s8 = (idx & 7) * 8;
        CP_ASYNC16(smem_u32(&Ks[row * 72 + s8]),
                   &QKV[baseK + (size_t)row * D3 + s8]);
        CP_ASYNC16(smem_u32(&Vs[row * 72 + s8]),
                   &QKV[baseV + (size_t)row * D3 + s8]);
    }
    if (t < 64) msk[t] = mask[(size_t)b * SEQ + t] ? -3.0e38f : 0.f;
    CP_COMMIT();
    CP_WAIT(0);
    __syncthreads();

    uint32_t qf[4][4];
    #pragma unroll
    for (int kc4 = 0; kc4 < 4; kc4++) {
        LDMX4(qf[kc4][0], qf[kc4][1], qf[kc4][2], qf[kc4][3],
              smem_u32(&Qs[(warp * 16 + a_row) * 72 + kc4 * 16 + a_col]));
    }

    float m0 = -3.0e38f, m1 = -3.0e38f, l0 = 0.f, l1 = 0.f;
    float oacc[8][4];
    #pragma unroll
    for (int nt = 0; nt < 8; nt++)
        #pragma unroll
        for (int c = 0; c < 4; c++) oacc[nt][c] = 0.f;

    const int ntiles = SEQ / 64;
    for (int kt = 0; kt < ntiles; kt++) {
        const int cur = kt & 1;
        const bool pref = (kt + 1 < ntiles);
        if (pref) {
            const int nxt = cur ^ 1;
            const int k0n = (kt + 1) * 64;
            #pragma unroll
            for (int i = 0; i < 2; i++) {
                int idx = t + i * 256, row = idx >> 3, s8 = (idx & 7) * 8;
                CP_ASYNC16(smem_u32(&Ks[nxt * KSTG + row * 72 + s8]),
                           &QKV[baseK + (size_t)(k0n + row) * D3 + s8]);
                CP_ASYNC16(smem_u32(&Vs[nxt * KSTG + row * 72 + s8]),
                           &QKV[baseV + (size_t)(k0n + row) * D3 + s8]);
            }
            if (t < 64) msk[nxt * 64 + t] =
                mask[(size_t)b * SEQ + k0n + t] ? -3.0e38f : 0.f;
            CP_COMMIT();
        }
        const __half* Kc = Ks + cur * KSTG;
        const __half* Vc = Vs + cur * KSTG;
        const float*  mc = msk + cur * 64;

        float sc[8][4];
        #pragma unroll
        for (int nt = 0; nt < 8; nt++)
            #pragma unroll
            for (int c = 0; c < 4; c++) sc[nt][c] = 0.f;

        #pragma unroll
        for (int kc4 = 0; kc4 < 4; kc4++) {
            const int kc = kc4 * 16;
            #pragma unroll
            for (int p = 0; p < 4; p++) {
                const int c = p * 16;
                uint32_t r0, r1, r2, r3;
                LDMX4(r0, r1, r2, r3,
                      smem_u32(&Kc[(c + b_row) * 72 + kc + b_col]));
                uint32_t b0[2] = {r0, r1};
                uint32_t b1[2] = {r2, r3};
                MMA_F16(sc[2*p],     qf[kc4], b0);
                MMA_F16(sc[2*p + 1], qf[kc4], b1);
            }
        }

        float tm0 = -3.0e38f, tm1 = -3.0e38f;
        #pragma unroll
        for (int nt = 0; nt < 8; nt++) {
            const float mk0 = mc[nt * 8 + 2 * tig];
            const float mk1 = mc[nt * 8 + 2 * tig + 1];
            sc[nt][0] = sc[nt][0] * 0.125f + mk0;
            sc[nt][1] = sc[nt][1] * 0.125f + mk1;
            sc[nt][2] = sc[nt][2] * 0.125f + mk0;
            sc[nt][3] = sc[nt][3] * 0.125f + mk1;
            tm0 = fmaxf(tm0, fmaxf(sc[nt][0], sc[nt][1]));
            tm1 = fmaxf(tm1, fmaxf(sc[nt][2], sc[nt][3]));
        }
        tm0 = fmaxf(tm0, __shfl_xor_sync(0xffffffffu, tm0, 1));
        tm0 = fmaxf(tm0, __shfl_xor_sync(0xffffffffu, tm0, 2));
        tm1 = fmaxf(tm1, __shfl_xor_sync(0xffffffffu, tm1, 1));
        tm1 = fmaxf(tm1, __shfl_xor_sync(0xffffffffu, tm1, 2));

        const float nm0 = fmaxf(m0, tm0), nm1 = fmaxf(m1, tm1);
        const float a0 = __expf(m0 - nm0), a1 = __expf(m1 - nm1);

        float ps0 = 0.f, ps1 = 0.f;
        #pragma unroll
        for (int nt = 0; nt < 8; nt++) {
            const float p0 = __expf(sc[nt][0] - nm0);
            const float p1 = __expf(sc[nt][1] - nm0);
            const float p2 = __expf(sc[nt][2] - nm1);
            const float p3 = __expf(sc[nt][3] - nm1);
            ps0 += p0 + p1; ps1 += p2 + p3;
            *(__half2*)&Ps[rA * 72 + nt * 8 + 2*tig]       = __floats2half2_rn(p0, p1);
            *(__half2*)&Ps[(rA + 8) * 72 + nt * 8 + 2*tig] = __floats2half2_rn(p2, p3);
        }
        ps0 += __shfl_xor_sync(0xffffffffu, ps0, 1);
        ps0 += __shfl_xor_sync(0xffffffffu, ps0, 2);
        ps1 += __shfl_xor_sync(0xffffffffu, ps1, 1);
        ps1 += __shfl_xor_sync(0xffffffffu, ps1, 2);

        l0 = l0 * a0 + ps0;  l1 = l1 * a1 + ps1;
        m0 = nm0;  m1 = nm1;
        #pragma unroll
        for (int nt = 0; nt < 8; nt++) {
            oacc[nt][0] *= a0; oacc[nt][1] *= a0;
            oacc[nt][2] *= a1; oacc[nt][3] *= a1;
        }
        __syncwarp();

        const int mi = lane >> 3, rr = lane & 7;
        #pragma unroll
        for (int kc4 = 0; kc4 < 4; kc4++) {
            const int kc = kc4 * 16;
            uint32_t af[4];
            LDMX4(af[0], af[1], af[2], af[3],
                  smem_u32(&Ps[(warp * 16 + a_row) * 72 + kc + a_col]));
            #pragma unroll
            for (int ntp = 0; ntp < 4; ntp++) {
                const int key = kc + ((mi & 1) << 3) + rr;
                const int dim = ntp * 16 + ((mi >> 1) << 3);
                uint32_t r0, r1, r2, r3;
                LDMX4_TRANS(r0, r1, r2, r3, smem_u32(&Vc[key * 72 + dim]));
                uint32_t b0[2] = {r0, r1};
                uint32_t b1[2] = {r2, r3};
                MMA_F16(oacc[2*ntp],     af, b0);
                MMA_F16(oacc[2*ntp + 1], af, b1);
            }
        }

        if (pref) CP_WAIT(0);
        __syncthreads();
    }

    const float i0 = 1.f / l0, i1 = 1.f / l1;
    #pragma unroll
    for (int nt = 0; nt < 8; nt++) {
        const int col = nt * 8 + 2 * tig;
        *(__half2*)&O[baseO + (size_t)(q0 + rA) * D_MODEL + col] =
            __floats2half2_rn(oacc[nt][0] * i0, oacc[nt][1] * i0);
        *(__half2*)&O[baseO + (size_t)(q0 + rA + 8) * D_MODEL + col] =
            __floats2half2_rn(oacc[nt][2] * i1, oacc[nt][3] * i1);
    }
}

// ---------------- launch ---------------------------------------------------
extern "C" void kernel_launch(void* const* d_in, const int* in_sizes, int n_in,
                              void* d_out, int out_size)
{
    const float* x     = (const float*)d_in[0];
    const unsigned char* mask = (const unsigned char*)d_in[1];
    const float* W_Q   = (const float*)d_in[2];
    const float* W_K   = (const float*)d_in[3];
    const float* W_V   = (const float*)d_in[4];
    const float* W_O   = (const float*)d_in[5];
    const float* W1    = (const float*)d_in[6];
    const float* b1    = (const float*)d_in[7];
    const float* W2    = (const float*)d_in[8];
    const float* b2    = (const float*)d_in[9];
    const float* g1    = (const float*)d_in[10];
    const float* beta1 = (const float*)d_in[11];
    const float* g2    = (const float*)d_in[12];
    const float* beta2 = (const float*)d_in[13];
    float* out = (float*)d_out;

    __half *h1, *qkv, *at, *h2, *f1;
    __half *wqkv, *wo, *w1, *w2;
    float *x1;
    cudaGetSymbolAddress((void**)&h1,   g_h1);
    cudaGetSymbolAddress((void**)&qkv,  g_qkv);
    cudaGetSymbolAddress((void**)&at,   g_at);
    cudaGetSymbolAddress((void**)&x1,   g_x1);
    cudaGetSymbolAddress((void**)&h2,   g_h2);
    cudaGetSymbolAddress((void**)&f1,   g_f1);
    cudaGetSymbolAddress((void**)&wqkv, g_wqkv);
    cudaGetSymbolAddress((void**)&wo,   g_wo);
    cudaGetSymbolAddress((void**)&w1,   g_w1);
    cudaGetSymbolAddress((void**)&w2,   g_w2);

    cudaFuncSetAttribute(attn_tc, cudaFuncAttributeMaxDynamicSharedMemorySize,
                         ASMEM_BYTES);
    cudaFuncSetAttribute(gemm_f16<0,1>, cudaFuncAttributeMaxDynamicSharedMemorySize, G_SMEM);
    cudaFuncSetAttribute(gemm_f16<2,0>, cudaFuncAttributeMaxDynamicSharedMemorySize, G_SMEM);
    cudaFuncSetAttribute(gemm_f16<1,1>, cudaFuncAttributeMaxDynamicSharedMemorySize, G_SMEM);
    cudaFuncSetAttribute(gemm_f16<3,0>, cudaFuncAttributeMaxDynamicSharedMemorySize, G_SMEM);

    const dim3 gQKV(D3/128,      NTOK/64);   // (24, 64)
    const dim3 gDD (D_MODEL/128, NTOK/64);   // (8, 64)
    const dim3 gDF (D_FF/128,    NTOK/64);   // (32, 64)
    const int DD4 = D_MODEL*D_MODEL/4, DF4 = D_FF*D_MODEL/4;

    // 0. weights -> fp16
    conv_qkv <<<3*DD4/256, 256>>>((const float4*)W_Q, (const float4*)W_K,
                                  (const float4*)W_V, wqkv);
    conv_rest<<<(DD4 + 2*DF4 + 255)/256, 256>>>((const float4*)W_O,
                                                (const float4*)W1,
                                                (const float4*)W2,
                                                wo, w1, w2);

    // 1. pre-LN
    ln_kernel<<<NTOK, 256>>>(x, g1, beta1, h1);
    // 2. fused QKV projection
    gemm_f16<0,1><<<gQKV, 256, G_SMEM>>>(h1, wqkv, qkv, NTOK, D3, D_MODEL, nullptr, nullptr);
    // 3. flash attention
    attn_tc<<<dim3(SEQ/128, HEADS, BATCH), 256, ASMEM_BYTES>>>(qkv, mask, at);
    // 4. output projection + residual (fp32 out)
    gemm_f16<2,0><<<gDD, 256, G_SMEM>>>(at, wo, x1, NTOK, D_MODEL, D_MODEL, nullptr, x);
    // 5. second LN
    ln_kernel<<<NTOK, 256>>>(x1, g2, beta2, h2);
    // 6. FFN1 (+b1)
    gemm_f16<1,1><<<gDF, 256, G_SMEM>>>(h2, w1, f1, NTOK, D_FF, D_MODEL, b1, nullptr);
    // 7. FFN2: relu(C + b2) + residual(x1), fp32 final
    gemm_f16<3,0><<<gDD, 256, G_SMEM>>>(f1, w2, out, NTOK, D_MODEL, D_FF, b2, x1);
}

// round 15
// speedup vs baseline: 1.2484x; 1.0405x over previous
#include <cuda_runtime.h>
#include <cuda_fp16.h>
#include <cstdint>
#include <cstddef>

#define D_MODEL 1024
#define D_FF    4096
#define HEADS   16
#define DKH     64
#define BATCH   2
#define SEQ     2048
#define NTOK    (BATCH*SEQ)
#define D3      (3*D_MODEL)

// ---------------- scratch (device globals; no allocations allowed) ----------
__device__ __half g_h1 [NTOK * D_MODEL];
__device__ __half g_qkv[NTOK * D3];
__device__ __half g_at [NTOK * D_MODEL];
__device__ float  g_x1 [NTOK * D_MODEL];
__device__ __half g_h2 [NTOK * D_MODEL];
__device__ __half g_f1 [NTOK * D_FF];
__device__ __half g_wqkv[D3 * D_MODEL];
__device__ __half g_wo[D_MODEL * D_MODEL];
__device__ __half g_w1[D_FF * D_MODEL];
__device__ __half g_w2[D_MODEL * D_FF];

// ---------------- helpers ---------------------------------------------------
__device__ __forceinline__ uint32_t smem_u32(const void* p) {
    return (uint32_t)__cvta_generic_to_shared(p);
}
#define CP_ASYNC16(dst, src) \
    asm volatile("cp.async.cg.shared.global [%0], [%1], 16;\n" :: "r"(dst), "l"(src))
#define CP_COMMIT() asm volatile("cp.async.commit_group;\n" ::: "memory")
#define CP_WAIT(n)  asm volatile("cp.async.wait_group %0;\n" :: "n"(n) : "memory")

#define MMA_F16(d, a, b) \
    asm volatile("mma.sync.aligned.m16n8k16.row.col.f32.f16.f16.f32 " \
                 "{%0,%1,%2,%3},{%4,%5,%6,%7},{%8,%9},{%0,%1,%2,%3};" \
                 : "+f"(d[0]), "+f"(d[1]), "+f"(d[2]), "+f"(d[3]) \
                 : "r"(a[0]), "r"(a[1]), "r"(a[2]), "r"(a[3]), \
                   "r"(b[0]), "r"(b[1]))

#define LDMX4(r0, r1, r2, r3, addr) \
    asm volatile("ldmatrix.sync.aligned.m8n8.x4.shared.b16 {%0,%1,%2,%3}, [%4];" \
                 : "=r"(r0), "=r"(r1), "=r"(r2), "=r"(r3) : "r"(addr))
#define LDMX4_TRANS(r0, r1, r2, r3, addr) \
    asm volatile("ldmatrix.sync.aligned.m8n8.x4.trans.shared.b16 {%0,%1,%2,%3}, [%4];" \
                 : "=r"(r0), "=r"(r1), "=r"(r2), "=r"(r3) : "r"(addr))

// ---------------- weight conversion -----------------------------------------
__global__ __launch_bounds__(256) void conv_qkv(const float4* __restrict__ q,
                                                const float4* __restrict__ k,
                                                const float4* __restrict__ v,
                                                __half* __restrict__ out)
{
    const int per = D_MODEL * D_MODEL / 4;
    int i = blockIdx.x * 256 + threadIdx.x;
    float4 val;
    if (i < per)            val = q[i];
    else if (i < 2 * per)   val = k[i - per];
    else                    val = v[i - 2 * per];
    __half2* o = (__half2*)(out + (size_t)i * 4);
    o[0] = __floats2half2_rn(val.x, val.y);
    o[1] = __floats2half2_rn(val.z, val.w);
}

__global__ __launch_bounds__(256) void conv_rest(const float4* __restrict__ wo_in,
                                                 const float4* __restrict__ w1_in,
                                                 const float4* __restrict__ w2_in,
                                                 __half* __restrict__ wo_out,
                                                 __half* __restrict__ w1_out,
                                                 __half* __restrict__ w2_out)
{
    const int nDD = D_MODEL * D_MODEL / 4;
    const int nDF = D_FF * D_MODEL / 4;
    int i = blockIdx.x * 256 + threadIdx.x;
    const float4* src; __half* dst; int j;
    if (i < nDD)             { src = wo_in; dst = wo_out; j = i; }
    else if (i < nDD + nDF)  { src = w1_in; dst = w1_out; j = i - nDD; }
    else if (i < nDD + 2*nDF){ src = w2_in; dst = w2_out; j = i - nDD - nDF; }
    else return;
    float4 v = src[j];
    __half2* o = (__half2*)(dst + (size_t)j * 4);
    o[0] = __floats2half2_rn(v.x, v.y);
    o[1] = __floats2half2_rn(v.z, v.w);
}

// ---------------- LayerNorm (single-pass) ------------------------------------
__global__ __launch_bounds__(256) void ln_kernel(const float* __restrict__ x,
                                                 const float* __restrict__ g,
                                                 const float* __restrict__ b,
                                                 __half* __restrict__ out)
{
    __shared__ float redS[8], redQ[8];
    __shared__ float bmu, brs;
    const int row = blockIdx.x;
    const int t = threadIdx.x;
    const int lane = t & 31, w = t >> 5;

    const float4* x4 = (const float4*)x + (size_t)row * 256;
    float4 v = x4[t];

    float s  = v.x + v.y + v.z + v.w;
    float s2 = v.x*v.x + v.y*v.y + v.z*v.z + v.w*v.w;
    #pragma unroll
    for (int o = 16; o; o >>= 1) {
        s  += __shfl_xor_sync(0xffffffffu, s, o);
        s2 += __shfl_xor_sync(0xffffffffu, s2, o);
    }
    if (lane == 0) { redS[w] = s; redQ[w] = s2; }
    __syncthreads();
    if (t == 0) {
        float ts = 0.f, tq = 0.f;
        #pragma unroll
        for (int i = 0; i < 8; i++) { ts += redS[i]; tq += redQ[i]; }
        const float mu = ts * (1.f / 1024.f);
        const float var = tq * (1.f / 1024.f) - mu * mu;
        bmu = mu;
        brs = rsqrtf(var + 1e-5f);
    }
    __syncthreads();
    const float mu = bmu, rs = brs;

    float4 gv = ((const float4*)g)[t];
    float4 bv = ((const float4*)b)[t];
    __half2* orow = (__half2*)(out + (size_t)row * 1024);
    orow[t*2]   = __floats2half2_rn((v.x - mu)*rs*gv.x + bv.x,
                                    (v.y - mu)*rs*gv.y + bv.y);
    orow[t*2+1] = __floats2half2_rn((v.z - mu)*rs*gv.z + bv.z,
                                    (v.w - mu)*rs*gv.w + bv.w);
}

// ---------------- FP16 tensor-core GEMM NT (64x128, 4 CTA/SM) ---------------
// C[N,M] = A[N,K] * B[M,K]^T.  CTA: 64 rows x 128 cols, BK=32, 8 warps in
// 2x4, warp tile 32x32.  3-stage cp.async ring (45KB smem), one sync/k-tile.
// launch_bounds(256,4) caps regs at 64 -> 4 CTA/SM (32 warps, ~46% occ).
// EPI: 0=none, 1=+bias, 2=+res, 3=relu(+bias)+res.  HOUT: 1 = store half.
#define GLDSH 40                     // 32 + 8 pad halves; 80B rows
#define G_ASTG (64*GLDSH)            // A stage halves
#define G_BSTG (128*GLDSH)           // B stage halves
#define G_NSTG 3
#define G_SMEM (G_NSTG*(G_ASTG+G_BSTG)*2)    // 46080 bytes

template<int EPI, int HOUT>
__global__ __launch_bounds__(256, 4) void gemm_f16(const __half* __restrict__ A,
                                                   const __half* __restrict__ B,
                                                   void* __restrict__ Cv,
                                                   int N, int M, int K,
                                                   const float* __restrict__ bias,
                                                   const float* __restrict__ res)
{
    extern __shared__ __align__(16) char sh[];
    __half* Ash = (__half*)sh;                     // [3][64][40]
    __half* Bsh = (__half*)sh + G_NSTG * G_ASTG;   // [3][128][40]

    const int t    = threadIdx.x;
    const int lane = t & 31;
    const int warp = t >> 5;
    const int wm   = warp >> 2;          // 0..1
    const int wn   = warp & 3;           // 0..3
    const int g    = lane >> 2;
    const int tig  = lane & 3;
    const int n0   = blockIdx.y * 64;
    const int m0   = blockIdx.x * 128;

    const int a_row = lane & 15;
    const int a_col = (lane >> 4) << 3;
    const int b_row = ((lane >> 4) << 3) + (lane & 7);
    const int b_col = ((lane >> 3) & 1) << 3;

    const int alr = t >> 2;              // 0..63
    const int ach = (t & 3) * 8;         // 0,8,16,24 halves
    const __half* Arp  = A + (size_t)(n0 + alr) * K + ach;
    const __half* Brp0 = B + (size_t)(m0 + alr) * K + ach;
    const __half* Brp1 = B + (size_t)(m0 + alr + 64) * K + ach;

    float acc[2][4][4];
    #pragma unroll
    for (int i = 0; i < 2; i++)
        #pragma unroll
        for (int j = 0; j < 4; j++)
            #pragma unroll
            for (int c = 0; c < 4; c++) acc[i][j][c] = 0.f;

    const int nK = K / 32;

    // prologue: tiles 0..1 into stages 0..1
    #pragma unroll
    for (int p = 0; p < 2; p++) {
        __half* As = Ash + p * G_ASTG;
        __half* Bs = Bsh + p * G_BSTG;
        const int ko = p * 32;
        CP_ASYNC16(smem_u32(&As[alr * GLDSH + ach]),        Arp + ko);
        CP_ASYNC16(smem_u32(&Bs[alr * GLDSH + ach]),        Brp0 + ko);
        CP_ASYNC16(smem_u32(&Bs[(alr + 64) * GLDSH + ach]), Brp1 + ko);
        CP_COMMIT();
    }

    int cur = 0;
    for (int kt = 0; kt < nK; kt++) {
        if (kt + 1 < nK) CP_WAIT(1); else CP_WAIT(0);
        __syncthreads();   // tile kt visible; orders reuse of stage (kt+2)%3

        // prefetch tile kt+2 into stage (cur+2)%3 (last read at kt-1)
        if (kt + 2 < nK) {
            int p = cur + 2; if (p >= 3) p -= 3;
            const int ko = (kt + 2) * 32;
            __half* As = Ash + p * G_ASTG;
            __half* Bs = Bsh + p * G_BSTG;
            CP_ASYNC16(smem_u32(&As[alr * GLDSH + ach]),        Arp + ko);
            CP_ASYNC16(smem_u32(&Bs[alr * GLDSH + ach]),        Brp0 + ko);
            CP_ASYNC16(smem_u32(&Bs[(alr + 64) * GLDSH + ach]), Brp1 + ko);
            CP_COMMIT();
        }

        const __half* As = Ash + cur * G_ASTG;
        const __half* Bs = Bsh + cur * G_BSTG;

        #pragma unroll
        for (int ks = 0; ks < 2; ks++) {
            const int kc = ks * 16;
            uint32_t af[2][4];
            #pragma unroll
            for (int mt = 0; mt < 2; mt++) {
                const int r = wm * 32 + mt * 16;
                LDMX4(af[mt][0], af[mt][1], af[mt][2], af[mt][3],
                      smem_u32(&As[(r + a_row) * GLDSH + kc + a_col]));
            }
            uint32_t bf[4][2];
            #pragma unroll
            for (int p = 0; p < 2; p++) {
                const int c = wn * 32 + p * 16;
                uint32_t r0, r1, r2, r3;
                LDMX4(r0, r1, r2, r3,
                      smem_u32(&Bs[(c + b_row) * GLDSH + kc + b_col]));
                bf[2*p][0] = r0;  bf[2*p][1] = r1;
                bf[2*p+1][0] = r2; bf[2*p+1][1] = r3;
            }
            #pragma unroll
            for (int mt = 0; mt < 2; mt++)
                #pragma unroll
                for (int nt = 0; nt < 4; nt++)
                    MMA_F16(acc[mt][nt], af[mt], bf[nt]);
        }
        if (++cur >= 3) cur = 0;
        // no trailing sync (stage reuse ordered by next leading sync)
    }

    #pragma unroll
    for (int mt = 0; mt < 2; mt++) {
        const int r0 = n0 + wm * 32 + mt * 16 + g;
        #pragma unroll
        for (int nt = 0; nt < 4; nt++) {
            const int col = m0 + wn * 32 + nt * 8 + 2 * tig;
            float2 v0 = make_float2(acc[mt][nt][0], acc[mt][nt][1]);
            float2 v1 = make_float2(acc[mt][nt][2], acc[mt][nt][3]);
            if (EPI == 1 || EPI == 3) {
                float2 bb = *(const float2*)&bias[col];
                v0.x += bb.x; v0.y += bb.y;
                v1.x += bb.x; v1.y += bb.y;
            }
            if (EPI == 3) {
                v0.x = fmaxf(v0.x, 0.f); v0.y = fmaxf(v0.y, 0.f);
                v1.x = fmaxf(v1.x, 0.f); v1.y = fmaxf(v1.y, 0.f);
            }
            if (EPI == 2 || EPI == 3) {
                float2 r0v = *(const float2*)&res[(size_t)r0 * M + col];
                float2 r1v = *(const float2*)&res[(size_t)(r0 + 8) * M + col];
                v0.x += r0v.x; v0.y += r0v.y;
                v1.x += r1v.x; v1.y += r1v.y;
            }
            if (HOUT) {
                __half* C = (__half*)Cv;
                *(__half2*)&C[(size_t)r0 * M + col]       = __floats2half2_rn(v0.x, v0.y);
                *(__half2*)&C[(size_t)(r0 + 8) * M + col] = __floats2half2_rn(v1.x, v1.y);
            } else {
                float* C = (float*)Cv;
                *(float2*)&C[(size_t)r0 * M + col]       = v0;
                *(float2*)&C[(size_t)(r0 + 8) * M + col] = v1;
            }
        }
    }
}

// ---------------- FP16 tensor-core flash attention (round-7, proven) --------
#define HQS  0
#define HKS  9216
#define HVS  18432
#define HPS  27648
#define HTOT 36864
#define AMSK_B (HTOT*2)
#define ASMEM_BYTES (AMSK_B + 2*64*4)
#define KSTG 4608

__global__ __launch_bounds__(256) void attn_tc(const __half* __restrict__ QKV,
                                               const unsigned char* __restrict__ mask,
                                               __half* __restrict__ O)
{
    extern __shared__ char shb[];
    __half* Qs  = (__half*)shb + HQS;
    __half* Ks  = (__half*)shb + HKS;
    __half* Vs  = (__half*)shb + HVS;
    __half* Ps  = (__half*)shb + HPS;
    float*  msk = (float*)(shb + AMSK_B);

    const int t    = threadIdx.x;
    const int lane = t & 31;
    const int warp = t >> 5;
    const int g    = lane >> 2;
    const int tig  = lane & 3;
    const int q0   = blockIdx.x * 128;
    const int h    = blockIdx.y;
    const int b    = blockIdx.z;
    const size_t baseQ = (size_t)b * SEQ * D3 + (size_t)h * DKH;
    const size_t baseK = baseQ + D_MODEL;
    const size_t baseV = baseQ + 2 * D_MODEL;
    const size_t baseO = (size_t)b * SEQ * D_MODEL + (size_t)h * DKH;
    const int rA = warp * 16 + g;

    const int a_row = lane & 15;
    const int a_col = (lane >> 4) << 3;
    const int b_row = ((lane >> 4) << 3) + (lane & 7);
    const int b_col = ((lane >> 3) & 1) << 3;

    #pragma unroll
    for (int i = 0; i < 4; i++) {
        int idx = t + i * 256, row = idx >> 3, s8 = (idx & 7) * 8;
        CP_ASYNC16(smem_u32(&Qs[row * 72 + s8]),
                   &QKV[baseQ + (size_t)(q0 + row) * D3 + s8]);
    }
    #pragma unroll
    for (int i = 0; i < 2; i++) {
        int idx = t + i * 256, row = idx >> 3, s8 = (idx & 7) * 8;
        CP_ASYNC16(smem_u32(&Ks[row * 72 + s8]),
                   &QKV[baseK + (size_t)row * D3 + s8]);
        CP_ASYNC16(smem_u32(&Vs[row * 72 + s8]),
                   &QKV[baseV + (size_t)row * D3 + s8]);
    }
    if (t < 64) msk[t] = mask[(size_t)b * SEQ + t] ? -3.0e38f : 0.f;
    CP_COMMIT();
    CP_WAIT(0);
    __syncthreads();

    uint32_t qf[4][4];
    #pragma unroll
    for (int kc4 = 0; kc4 < 4; kc4++) {
        LDMX4(qf[kc4][0], qf[kc4][1], qf[kc4][2], qf[kc4][3],
              smem_u32(&Qs[(warp * 16 + a_row) * 72 + kc4 * 16 + a_col]));
    }

    float m0 = -3.0e38f, m1 = -3.0e38f, l0 = 0.f, l1 = 0.f;
    float oacc[8][4];
    #pragma unroll
    for (int nt = 0; nt < 8; nt++)
        #pragma unroll
        for (int c = 0; c < 4; c++) oacc[nt][c] = 0.f;

    const int ntiles = SEQ / 64;
    for (int kt = 0; kt < ntiles; kt++) {
        const int cur = kt & 1;
        const bool pref = (kt + 1 < ntiles);
        if (pref) {
            const int nxt = cur ^ 1;
            const int k0n = (kt + 1) * 64;
            #pragma unroll
            for (int i = 0; i < 2; i++) {
                int idx = t + i * 256, row = idx >> 3, s8 = (idx & 7) * 8;
                CP_ASYNC16(smem_u32(&Ks[nxt * KSTG + row * 72 + s8]),
                           &QKV[baseK + (size_t)(k0n + row) * D3 + s8]);
                CP_ASYNC16(smem_u32(&Vs[nxt * KSTG + row * 72 + s8]),
                           &QKV[baseV + (size_t)(k0n + row) * D3 + s8]);
            }
            if (t < 64) msk[nxt * 64 + t] =
                mask[(size_t)b * SEQ + k0n + t] ? -3.0e38f : 0.f;
            CP_COMMIT();
        }
        const __half* Kc = Ks + cur * KSTG;
        const __half* Vc = Vs + cur * KSTG;
        const float*  mc = msk + cur * 64;

        float sc[8][4];
        #pragma unroll
        for (int nt = 0; nt < 8; nt++)
            #pragma unroll
            for (int c = 0; c < 4; c++) sc[nt][c] = 0.f;

        #pragma unroll
        for (int kc4 = 0; kc4 < 4; kc4++) {
            const int kc = kc4 * 16;
            #pragma unroll
            for (int p = 0; p < 4; p++) {
                const int c = p * 16;
                uint32_t r0, r1, r2, r3;
                LDMX4(r0, r1, r2, r3,
                      smem_u32(&Kc[(c + b_row) * 72 + kc + b_col]));
                uint32_t b0[2] = {r0, r1};
                uint32_t b1[2] = {r2, r3};
                MMA_F16(sc[2*p],     qf[kc4], b0);
                MMA_F16(sc[2*p + 1], qf[kc4], b1);
            }
        }

        float tm0 = -3.0e38f, tm1 = -3.0e38f;
        #pragma unroll
        for (int nt = 0; nt < 8; nt++) {
            const float mk0 = mc[nt * 8 + 2 * tig];
            const float mk1 = mc[nt * 8 + 2 * tig + 1];
            sc[nt][0] = sc[nt][0] * 0.125f + mk0;
            sc[nt][1] = sc[nt][1] * 0.125f + mk1;
            sc[nt][2] = sc[nt][2] * 0.125f + mk0;
            sc[nt][3] = sc[nt][3] * 0.125f + mk1;
            tm0 = fmaxf(tm0, fmaxf(sc[nt][0], sc[nt][1]));
            tm1 = fmaxf(tm1, fmaxf(sc[nt][2], sc[nt][3]));
        }
        tm0 = fmaxf(tm0, __shfl_xor_sync(0xffffffffu, tm0, 1));
        tm0 = fmaxf(tm0, __shfl_xor_sync(0xffffffffu, tm0, 2));
        tm1 = fmaxf(tm1, __shfl_xor_sync(0xffffffffu, tm1, 1));
        tm1 = fmaxf(tm1, __shfl_xor_sync(0xffffffffu, tm1, 2));

        const float nm0 = fmaxf(m0, tm0), nm1 = fmaxf(m1, tm1);
        const float a0 = __expf(m0 - nm0), a1 = __expf(m1 - nm1);

        float ps0 = 0.f, ps1 = 0.f;
        #pragma unroll
        for (int nt = 0; nt < 8; nt++) {
            const float p0 = __expf(sc[nt][0] - nm0);
            const float p1 = __expf(sc[nt][1] - nm0);
            const float p2 = __expf(sc[nt][2] - nm1);
            const float p3 = __expf(sc[nt][3] - nm1);
            ps0 += p0 + p1; ps1 += p2 + p3;
            *(__half2*)&Ps[rA * 72 + nt * 8 + 2*tig]       = __floats2half2_rn(p0, p1);
            *(__half2*)&Ps[(rA + 8) * 72 + nt * 8 + 2*tig] = __floats2half2_rn(p2, p3);
        }
        ps0 += __shfl_xor_sync(0xffffffffu, ps0, 1);
        ps0 += __shfl_xor_sync(0xffffffffu, ps0, 2);
        ps1 += __shfl_xor_sync(0xffffffffu, ps1, 1);
        ps1 += __shfl_xor_sync(0xffffffffu, ps1, 2);

        l0 = l0 * a0 + ps0;  l1 = l1 * a1 + ps1;
        m0 = nm0;  m1 = nm1;
        #pragma unroll
        for (int nt = 0; nt < 8; nt++) {
            oacc[nt][0] *= a0; oacc[nt][1] *= a0;
            oacc[nt][2] *= a1; oacc[nt][3] *= a1;
        }
        __syncwarp();

        const int mi = lane >> 3, rr = lane & 7;
        #pragma unroll
        for (int kc4 = 0; kc4 < 4; kc4++) {
            const int kc = kc4 * 16;
            uint32_t af[4];
            LDMX4(af[0], af[1], af[2], af[3],
                  smem_u32(&Ps[(warp * 16 + a_row) * 72 + kc + a_col]));
            #pragma unroll
            for (int ntp = 0; ntp < 4; ntp++) {
                const int key = kc + ((mi & 1) << 3) + rr;
                const int dim = ntp * 16 + ((mi >> 1) << 3);
                uint32_t r0, r1, r2, r3;
                LDMX4_TRANS(r0, r1, r2, r3, smem_u32(&Vc[key * 72 + dim]));
                uint32_t b0[2] = {r0, r1};
                uint32_t b1[2] = {r2, r3};
                MMA_F16(oacc[2*ntp],     af, b0);
                MMA_F16(oacc[2*ntp + 1], af, b1);
            }
        }

        if (pref) CP_WAIT(0);
        __syncthreads();
    }

    const float i0 = 1.f / l0, i1 = 1.f / l1;
    #pragma unroll
    for (int nt = 0; nt < 8; nt++) {
        const int col = nt * 8 + 2 * tig;
        *(__half2*)&O[baseO + (size_t)(q0 + rA) * D_MODEL + col] =
            __floats2half2_rn(oacc[nt][0] * i0, oacc[nt][1] * i0);
        *(__half2*)&O[baseO + (size_t)(q0 + rA + 8) * D_MODEL + col] =
            __floats2half2_rn(oacc[nt][2] * i1, oacc[nt][3] * i1);
    }
}

// ---------------- launch ---------------------------------------------------
extern "C" void kernel_launch(void* const* d_in, const int* in_sizes, int n_in,
                              void* d_out, int out_size)
{
    const float* x     = (const float*)d_in[0];
    const unsigned char* mask = (const unsigned char*)d_in[1];
    const float* W_Q   = (const float*)d_in[2];
    const float* W_K   = (const float*)d_in[3];
    const float* W_V   = (const float*)d_in[4];
    const float* W_O   = (const float*)d_in[5];
    const float* W1    = (const float*)d_in[6];
    const float* b1    = (const float*)d_in[7];
    const float* W2    = (const float*)d_in[8];
    const float* b2    = (const float*)d_in[9];
    const float* g1    = (const float*)d_in[10];
    const float* beta1 = (const float*)d_in[11];
    const float* g2    = (const float*)d_in[12];
    const float* beta2 = (const float*)d_in[13];
    float* out = (float*)d_out;

    __half *h1, *qkv, *at, *h2, *f1;
    __half *wqkv, *wo, *w1, *w2;
    float *x1;
    cudaGetSymbolAddress((void**)&h1,   g_h1);
    cudaGetSymbolAddress((void**)&qkv,  g_qkv);
    cudaGetSymbolAddress((void**)&at,   g_at);
    cudaGetSymbolAddress((void**)&x1,   g_x1);
    cudaGetSymbolAddress((void**)&h2,   g_h2);
    cudaGetSymbolAddress((void**)&f1,   g_f1);
    cudaGetSymbolAddress((void**)&wqkv, g_wqkv);
    cudaGetSymbolAddress((void**)&wo,   g_wo);
    cudaGetSymbolAddress((void**)&w1,   g_w1);
    cudaGetSymbolAddress((void**)&w2,   g_w2);

    cudaFuncSetAttribute(attn_tc, cudaFuncAttributeMaxDynamicSharedMemorySize,
                         ASMEM_BYTES);
    cudaFuncSetAttribute(gemm_f16<0,1>, cudaFuncAttributeMaxDynamicSharedMemorySize, G_SMEM);
    cudaFuncSetAttribute(gemm_f16<2,0>, cudaFuncAttributeMaxDynamicSharedMemorySize, G_SMEM);
    cudaFuncSetAttribute(gemm_f16<1,1>, cudaFuncAttributeMaxDynamicSharedMemorySize, G_SMEM);
    cudaFuncSetAttribute(gemm_f16<3,0>, cudaFuncAttributeMaxDynamicSharedMemorySize, G_SMEM);

    const dim3 gQKV(D3/128,      NTOK/64);   // (24, 64)
    const dim3 gDD (D_MODEL/128, NTOK/64);   // (8, 64)
    const dim3 gDF (D_FF/128,    NTOK/64);   // (32, 64)
    const int DD4 = D_MODEL*D_MODEL/4, DF4 = D_FF*D_MODEL/4;

    // 0. weights -> fp16
    conv_qkv <<<3*DD4/256, 256>>>((const float4*)W_Q, (const float4*)W_K,
                                  (const float4*)W_V, wqkv);
    conv_rest<<<(DD4 + 2*DF4 + 255)/256, 256>>>((const float4*)W_O,
                                                (const float4*)W1,
                                                (const float4*)W2,
                                                wo, w1, w2);

    // 1. pre-LN
    ln_kernel<<<NTOK, 256>>>(x, g1, beta1, h1);
    // 2. fused QKV projection
    gemm_f16<0,1><<<gQKV, 256, G_SMEM>>>(h1, wqkv, qkv, NTOK, D3, D_MODEL, nullptr, nullptr);
    // 3. flash attention
    attn_tc<<<dim3(SEQ/128, HEADS, BATCH), 256, ASMEM_BYTES>>>(qkv, mask, at);
    // 4. output projection + residual (fp32 out)
    gemm_f16<2,0><<<gDD, 256, G_SMEM>>>(at, wo, x1, NTOK, D_MODEL, D_MODEL, nullptr, x);
    // 5. second LN
    ln_kernel<<<NTOK, 256>>>(x1, g2, beta2, h2);
    // 6. FFN1 (+b1)
    gemm_f16<1,1><<<gDF, 256, G_SMEM>>>(h2, w1, f1, NTOK, D_FF, D_MODEL, b1, nullptr);
    // 7. FFN2: relu(C + b2) + residual(x1), fp32 final
    gemm_f16<3,0><<<gDD, 256, G_SMEM>>>(f1, w2, out, NTOK, D_MODEL, D_FF, b2, x1);
}

// round 16
// speedup vs baseline: 1.2525x; 1.0033x over previous
#include <cuda_runtime.h>
#include <cuda_fp16.h>
#include <cstdint>
#include <cstddef>

#define D_MODEL 1024
#define D_FF    4096
#define HEADS   16
#define DKH     64
#define BATCH   2
#define SEQ     2048
#define NTOK    (BATCH*SEQ)
#define D3      (3*D_MODEL)

// ---------------- scratch (device globals; no allocations allowed) ----------
__device__ __half g_h1 [NTOK * D_MODEL];
__device__ __half g_qkv[NTOK * D3];
__device__ __half g_at [NTOK * D_MODEL];
__device__ float  g_x1 [NTOK * D_MODEL];
__device__ __half g_h2 [NTOK * D_MODEL];
__device__ __half g_f1 [NTOK * D_FF];
__device__ __half g_wqkv[D3 * D_MODEL];
__device__ __half g_wo[D_MODEL * D_MODEL];
__device__ __half g_w1[D_FF * D_MODEL];
__device__ __half g_w2[D_MODEL * D_FF];

// ---------------- helpers ---------------------------------------------------
__device__ __forceinline__ uint32_t smem_u32(const void* p) {
    return (uint32_t)__cvta_generic_to_shared(p);
}
#define CP_ASYNC16(dst, src) \
    asm volatile("cp.async.cg.shared.global [%0], [%1], 16;\n" :: "r"(dst), "l"(src))
#define CP_COMMIT() asm volatile("cp.async.commit_group;\n" ::: "memory")
#define CP_WAIT(n)  asm volatile("cp.async.wait_group %0;\n" :: "n"(n) : "memory")

#define MMA_F16(d, a, b) \
    asm volatile("mma.sync.aligned.m16n8k16.row.col.f32.f16.f16.f32 " \
                 "{%0,%1,%2,%3},{%4,%5,%6,%7},{%8,%9},{%0,%1,%2,%3};" \
                 : "+f"(d[0]), "+f"(d[1]), "+f"(d[2]), "+f"(d[3]) \
                 : "r"(a[0]), "r"(a[1]), "r"(a[2]), "r"(a[3]), \
                   "r"(b[0]), "r"(b[1]))

#define LDMX4(r0, r1, r2, r3, addr) \
    asm volatile("ldmatrix.sync.aligned.m8n8.x4.shared.b16 {%0,%1,%2,%3}, [%4];" \
                 : "=r"(r0), "=r"(r1), "=r"(r2), "=r"(r3) : "r"(addr))
#define LDMX4_TRANS(r0, r1, r2, r3, addr) \
    asm volatile("ldmatrix.sync.aligned.m8n8.x4.trans.shared.b16 {%0,%1,%2,%3}, [%4];" \
                 : "=r"(r0), "=r"(r1), "=r"(r2), "=r"(r3) : "r"(addr))

// ---------------- weight conversion -----------------------------------------
__global__ __launch_bounds__(256) void conv_qkv(const float4* __restrict__ q,
                                                const float4* __restrict__ k,
                                                const float4* __restrict__ v,
                                                __half* __restrict__ out)
{
    const int per = D_MODEL * D_MODEL / 4;
    int i = blockIdx.x * 256 + threadIdx.x;
    float4 val;
    if (i < per)            val = q[i];
    else if (i < 2 * per)   val = k[i - per];
    else                    val = v[i - 2 * per];
    __half2* o = (__half2*)(out + (size_t)i * 4);
    o[0] = __floats2half2_rn(val.x, val.y);
    o[1] = __floats2half2_rn(val.z, val.w);
}

__global__ __launch_bounds__(256) void conv_rest(const float4* __restrict__ wo_in,
                                                 const float4* __restrict__ w1_in,
                                                 const float4* __restrict__ w2_in,
                                                 __half* __restrict__ wo_out,
                                                 __half* __restrict__ w1_out,
                                                 __half* __restrict__ w2_out)
{
    const int nDD = D_MODEL * D_MODEL / 4;
    const int nDF = D_FF * D_MODEL / 4;
    int i = blockIdx.x * 256 + threadIdx.x;
    const float4* src; __half* dst; int j;
    if (i < nDD)             { src = wo_in; dst = wo_out; j = i; }
    else if (i < nDD + nDF)  { src = w1_in; dst = w1_out; j = i - nDD; }
    else if (i < nDD + 2*nDF){ src = w2_in; dst = w2_out; j = i - nDD - nDF; }
    else return;
    float4 v = src[j];
    __half2* o = (__half2*)(dst + (size_t)j * 4);
    o[0] = __floats2half2_rn(v.x, v.y);
    o[1] = __floats2half2_rn(v.z, v.w);
}

// ---------------- LayerNorm (single-pass) ------------------------------------
__global__ __launch_bounds__(256) void ln_kernel(const float* __restrict__ x,
                                                 const float* __restrict__ g,
                                                 const float* __restrict__ b,
                                                 __half* __restrict__ out)
{
    __shared__ float redS[8], redQ[8];
    __shared__ float bmu, brs;
    const int row = blockIdx.x;
    const int t = threadIdx.x;
    const int lane = t & 31, w = t >> 5;

    const float4* x4 = (const float4*)x + (size_t)row * 256;
    float4 v = x4[t];

    float s  = v.x + v.y + v.z + v.w;
    float s2 = v.x*v.x + v.y*v.y + v.z*v.z + v.w*v.w;
    #pragma unroll
    for (int o = 16; o; o >>= 1) {
        s  += __shfl_xor_sync(0xffffffffu, s, o);
        s2 += __shfl_xor_sync(0xffffffffu, s2, o);
    }
    if (lane == 0) { redS[w] = s; redQ[w] = s2; }
    __syncthreads();
    if (t == 0) {
        float ts = 0.f, tq = 0.f;
        #pragma unroll
        for (int i = 0; i < 8; i++) { ts += redS[i]; tq += redQ[i]; }
        const float mu = ts * (1.f / 1024.f);
        const float var = tq * (1.f / 1024.f) - mu * mu;
        bmu = mu;
        brs = rsqrtf(var + 1e-5f);
    }
    __syncthreads();
    const float mu = bmu, rs = brs;

    float4 gv = ((const float4*)g)[t];
    float4 bv = ((const float4*)b)[t];
    __half2* orow = (__half2*)(out + (size_t)row * 1024);
    orow[t*2]   = __floats2half2_rn((v.x - mu)*rs*gv.x + bv.x,
                                    (v.y - mu)*rs*gv.y + bv.y);
    orow[t*2+1] = __floats2half2_rn((v.z - mu)*rs*gv.z + bv.z,
                                    (v.w - mu)*rs*gv.w + bv.w);
}

// ---------------- FP16 tensor-core GEMM NT (R15, proven: 4 CTA/SM) ----------
#define GLDSH 40                     // 32 + 8 pad halves; 80B rows
#define G_ASTG (64*GLDSH)
#define G_BSTG (128*GLDSH)
#define G_NSTG 3
#define G_SMEM (G_NSTG*(G_ASTG+G_BSTG)*2)    // 46080 bytes

template<int EPI, int HOUT>
__global__ __launch_bounds__(256, 4) void gemm_f16(const __half* __restrict__ A,
                                                   const __half* __restrict__ B,
                                                   void* __restrict__ Cv,
                                                   int N, int M, int K,
                                                   const float* __restrict__ bias,
                                                   const float* __restrict__ res)
{
    extern __shared__ __align__(16) char sh[];
    __half* Ash = (__half*)sh;                     // [3][64][40]
    __half* Bsh = (__half*)sh + G_NSTG * G_ASTG;   // [3][128][40]

    const int t    = threadIdx.x;
    const int lane = t & 31;
    const int warp = t >> 5;
    const int wm   = warp >> 2;
    const int wn   = warp & 3;
    const int g    = lane >> 2;
    const int tig  = lane & 3;
    const int n0   = blockIdx.y * 64;
    const int m0   = blockIdx.x * 128;

    const int a_row = lane & 15;
    const int a_col = (lane >> 4) << 3;
    const int b_row = ((lane >> 4) << 3) + (lane & 7);
    const int b_col = ((lane >> 3) & 1) << 3;

    const int alr = t >> 2;
    const int ach = (t & 3) * 8;
    const __half* Arp  = A + (size_t)(n0 + alr) * K + ach;
    const __half* Brp0 = B + (size_t)(m0 + alr) * K + ach;
    const __half* Brp1 = B + (size_t)(m0 + alr + 64) * K + ach;

    float acc[2][4][4];
    #pragma unroll
    for (int i = 0; i < 2; i++)
        #pragma unroll
        for (int j = 0; j < 4; j++)
            #pragma unroll
            for (int c = 0; c < 4; c++) acc[i][j][c] = 0.f;

    const int nK = K / 32;

    #pragma unroll
    for (int p = 0; p < 2; p++) {
        __half* As = Ash + p * G_ASTG;
        __half* Bs = Bsh + p * G_BSTG;
        const int ko = p * 32;
        CP_ASYNC16(smem_u32(&As[alr * GLDSH + ach]),        Arp + ko);
        CP_ASYNC16(smem_u32(&Bs[alr * GLDSH + ach]),        Brp0 + ko);
        CP_ASYNC16(smem_u32(&Bs[(alr + 64) * GLDSH + ach]), Brp1 + ko);
        CP_COMMIT();
    }

    int cur = 0;
    for (int kt = 0; kt < nK; kt++) {
        if (kt + 1 < nK) CP_WAIT(1); else CP_WAIT(0);
        __syncthreads();

        if (kt + 2 < nK) {
            int p = cur + 2; if (p >= 3) p -= 3;
            const int ko = (kt + 2) * 32;
            __half* As = Ash + p * G_ASTG;
            __half* Bs = Bsh + p * G_BSTG;
            CP_ASYNC16(smem_u32(&As[alr * GLDSH + ach]),        Arp + ko);
            CP_ASYNC16(smem_u32(&Bs[alr * GLDSH + ach]),        Brp0 + ko);
            CP_ASYNC16(smem_u32(&Bs[(alr + 64) * GLDSH + ach]), Brp1 + ko);
            CP_COMMIT();
        }

        const __half* As = Ash + cur * G_ASTG;
        const __half* Bs = Bsh + cur * G_BSTG;

        #pragma unroll
        for (int ks = 0; ks < 2; ks++) {
            const int kc = ks * 16;
            uint32_t af[2][4];
            #pragma unroll
            for (int mt = 0; mt < 2; mt++) {
                const int r = wm * 32 + mt * 16;
                LDMX4(af[mt][0], af[mt][1], af[mt][2], af[mt][3],
                      smem_u32(&As[(r + a_row) * GLDSH + kc + a_col]));
            }
            uint32_t bf[4][2];
            #pragma unroll
            for (int p = 0; p < 2; p++) {
                const int c = wn * 32 + p * 16;
                uint32_t r0, r1, r2, r3;
                LDMX4(r0, r1, r2, r3,
                      smem_u32(&Bs[(c + b_row) * GLDSH + kc + b_col]));
                bf[2*p][0] = r0;  bf[2*p][1] = r1;
                bf[2*p+1][0] = r2; bf[2*p+1][1] = r3;
            }
            #pragma unroll
            for (int mt = 0; mt < 2; mt++)
                #pragma unroll
                for (int nt = 0; nt < 4; nt++)
                    MMA_F16(acc[mt][nt], af[mt], bf[nt]);
        }
        if (++cur >= 3) cur = 0;
    }

    #pragma unroll
    for (int mt = 0; mt < 2; mt++) {
        const int r0 = n0 + wm * 32 + mt * 16 + g;
        #pragma unroll
        for (int nt = 0; nt < 4; nt++) {
            const int col = m0 + wn * 32 + nt * 8 + 2 * tig;
            float2 v0 = make_float2(acc[mt][nt][0], acc[mt][nt][1]);
            float2 v1 = make_float2(acc[mt][nt][2], acc[mt][nt][3]);
            if (EPI == 1 || EPI == 3) {
                float2 bb = *(const float2*)&bias[col];
                v0.x += bb.x; v0.y += bb.y;
                v1.x += bb.x; v1.y += bb.y;
            }
            if (EPI == 3) {
                v0.x = fmaxf(v0.x, 0.f); v0.y = fmaxf(v0.y, 0.f);
                v1.x = fmaxf(v1.x, 0.f); v1.y = fmaxf(v1.y, 0.f);
            }
            if (EPI == 2 || EPI == 3) {
                float2 r0v = *(const float2*)&res[(size_t)r0 * M + col];
                float2 r1v = *(const float2*)&res[(size_t)(r0 + 8) * M + col];
                v0.x += r0v.x; v0.y += r0v.y;
                v1.x += r1v.x; v1.y += r1v.y;
            }
            if (HOUT) {
                __half* C = (__half*)Cv;
                *(__half2*)&C[(size_t)r0 * M + col]       = __floats2half2_rn(v0.x, v0.y);
                *(__half2*)&C[(size_t)(r0 + 8) * M + col] = __floats2half2_rn(v1.x, v1.y);
            } else {
                float* C = (float*)Cv;
                *(float2*)&C[(size_t)r0 * M + col]       = v0;
                *(float2*)&C[(size_t)(r0 + 8) * M + col] = v1;
            }
        }
    }
}

// ---------------- FP16 flash attention (3-stage K/V ring, 1 sync/tile) ------
#define KSTG 4608                    // 64*72 halves per K or V stage
#define HQS  0                       // Qs [128][72]
#define HKS  9216                    // Ks [3][64][72]
#define HVS  (9216 + 3*KSTG)         // Vs [3][64][72]
#define HPS  (HVS + 3*KSTG)          // Ps [128][72]
#define HTOT (HPS + 9216)
#define AMSK_B (HTOT*2)              // msk [3][64] fp32
#define ASMEM_BYTES (AMSK_B + 3*64*4)

__global__ __launch_bounds__(256) void attn_tc(const __half* __restrict__ QKV,
                                               const unsigned char* __restrict__ mask,
                                               __half* __restrict__ O)
{
    extern __shared__ char shb[];
    __half* Qs  = (__half*)shb + HQS;
    __half* Ks  = (__half*)shb + HKS;
    __half* Vs  = (__half*)shb + HVS;
    __half* Ps  = (__half*)shb + HPS;
    float*  msk = (float*)(shb + AMSK_B);

    const int t    = threadIdx.x;
    const int lane = t & 31;
    const int warp = t >> 5;
    const int g    = lane >> 2;
    const int tig  = lane & 3;
    const int q0   = blockIdx.x * 128;
    const int h    = blockIdx.y;
    const int b    = blockIdx.z;
    const size_t baseQ = (size_t)b * SEQ * D3 + (size_t)h * DKH;
    const size_t baseK = baseQ + D_MODEL;
    const size_t baseV = baseQ + 2 * D_MODEL;
    const size_t baseO = (size_t)b * SEQ * D_MODEL + (size_t)h * DKH;
    const int rA = warp * 16 + g;

    const int a_row = lane & 15;
    const int a_col = (lane >> 4) << 3;
    const int b_row = ((lane >> 4) << 3) + (lane & 7);
    const int b_col = ((lane >> 3) & 1) << 3;

    // prologue: group0 = Q + K/V tile0 (stage 0); group1 = K/V tile1 (stage 1)
    #pragma unroll
    for (int i = 0; i < 4; i++) {
        int idx = t + i * 256, row = idx >> 3, s8 = (idx & 7) * 8;
        CP_ASYNC16(smem_u32(&Qs[row * 72 + s8]),
                   &QKV[baseQ + (size_t)(q0 + row) * D3 + s8]);
    }
    #pragma unroll
    for (int i = 0; i < 2; i++) {
        int idx = t + i * 256, row = idx >> 3, s8 = (idx & 7) * 8;
        CP_ASYNC16(smem_u32(&Ks[row * 72 + s8]),
                   &QKV[baseK + (size_t)row * D3 + s8]);
        CP_ASYNC16(smem_u32(&Vs[row * 72 + s8]),
                   &QKV[baseV + (size_t)row * D3 + s8]);
    }
    CP_COMMIT();
    #pragma unroll
    for (int i = 0; i < 2; i++) {
        int idx = t + i * 256, row = idx >> 3, s8 = (idx & 7) * 8;
        CP_ASYNC16(smem_u32(&Ks[KSTG + row * 72 + s8]),
                   &QKV[baseK + (size_t)(64 + row) * D3 + s8]);
        CP_ASYNC16(smem_u32(&Vs[KSTG + row * 72 + s8]),
                   &QKV[baseV + (size_t)(64 + row) * D3 + s8]);
    }
    CP_COMMIT();
    if (t < 64) {
        msk[t]      = mask[(size_t)b * SEQ + t]      ? -3.0e38f : 0.f;
        msk[64 + t] = mask[(size_t)b * SEQ + 64 + t] ? -3.0e38f : 0.f;
    }

    float m0 = -3.0e38f, m1 = -3.0e38f, l0 = 0.f, l1 = 0.f;
    float oacc[8][4];
    #pragma unroll
    for (int nt = 0; nt < 8; nt++)
        #pragma unroll
        for (int c = 0; c < 4; c++) oacc[nt][c] = 0.f;

    uint32_t qf[4][4];
    const int ntiles = SEQ / 64;
    int cur = 0;
    for (int kt = 0; kt < ntiles; kt++) {
        if (kt + 1 < ntiles) CP_WAIT(1); else CP_WAIT(0);
        __syncthreads();   // tile kt visible; orders reuse of stage (kt+2)%3

        if (kt == 0) {     // Q arrived with group0; preload frags once
            #pragma unroll
            for (int kc4 = 0; kc4 < 4; kc4++)
                LDMX4(qf[kc4][0], qf[kc4][1], qf[kc4][2], qf[kc4][3],
                      smem_u32(&Qs[(warp * 16 + a_row) * 72 + kc4 * 16 + a_col]));
        }

        // prefetch tile kt+2 into stage (cur+2)%3 (last read at kt-1)
        if (kt + 2 < ntiles) {
            int p = cur + 2; if (p >= 3) p -= 3;
            const int k0n = (kt + 2) * 64;
            #pragma unroll
            for (int i = 0; i < 2; i++) {
                int idx = t + i * 256, row = idx >> 3, s8 = (idx & 7) * 8;
                CP_ASYNC16(smem_u32(&Ks[p * KSTG + row * 72 + s8]),
                           &QKV[baseK + (size_t)(k0n + row) * D3 + s8]);
                CP_ASYNC16(smem_u32(&Vs[p * KSTG + row * 72 + s8]),
                           &QKV[baseV + (size_t)(k0n + row) * D3 + s8]);
            }
            CP_COMMIT();
            if (t < 64) msk[p * 64 + t] =
                mask[(size_t)b * SEQ + k0n + t] ? -3.0e38f : 0.f;
        }

        const __half* Kc = Ks + cur * KSTG;
        const __half* Vc = Vs + cur * KSTG;
        const float*  mc = msk + cur * 64;

        // ---- S = Q K^T ----
        float sc[8][4];
        #pragma unroll
        for (int nt = 0; nt < 8; nt++)
            #pragma unroll
            for (int c = 0; c < 4; c++) sc[nt][c] = 0.f;

        #pragma unroll
        for (int kc4 = 0; kc4 < 4; kc4++) {
            const int kc = kc4 * 16;
            #pragma unroll
            for (int p = 0; p < 4; p++) {
                const int c = p * 16;
                uint32_t r0, r1, r2, r3;
                LDMX4(r0, r1, r2, r3,
                      smem_u32(&Kc[(c + b_row) * 72 + kc + b_col]));
                uint32_t b0[2] = {r0, r1};
                uint32_t b1[2] = {r2, r3};
                MMA_F16(sc[2*p],     qf[kc4], b0);
                MMA_F16(sc[2*p + 1], qf[kc4], b1);
            }
        }

        // ---- scale + mask + row stats ----
        float tm0 = -3.0e38f, tm1 = -3.0e38f;
        #pragma unroll
        for (int nt = 0; nt < 8; nt++) {
            const float mk0 = mc[nt * 8 + 2 * tig];
            const float mk1 = mc[nt * 8 + 2 * tig + 1];
            sc[nt][0] = sc[nt][0] * 0.125f + mk0;
            sc[nt][1] = sc[nt][1] * 0.125f + mk1;
            sc[nt][2] = sc[nt][2] * 0.125f + mk0;
            sc[nt][3] = sc[nt][3] * 0.125f + mk1;
            tm0 = fmaxf(tm0, fmaxf(sc[nt][0], sc[nt][1]));
            tm1 = fmaxf(tm1, fmaxf(sc[nt][2], sc[nt][3]));
        }
        tm0 = fmaxf(tm0, __shfl_xor_sync(0xffffffffu, tm0, 1));
        tm0 = fmaxf(tm0, __shfl_xor_sync(0xffffffffu, tm0, 2));
        tm1 = fmaxf(tm1, __shfl_xor_sync(0xffffffffu, tm1, 1));
        tm1 = fmaxf(tm1, __shfl_xor_sync(0xffffffffu, tm1, 2));

        const float nm0 = fmaxf(m0, tm0), nm1 = fmaxf(m1, tm1);
        const float a0 = __expf(m0 - nm0), a1 = __expf(m1 - nm1);

        float ps0 = 0.f, ps1 = 0.f;
        #pragma unroll
        for (int nt = 0; nt < 8; nt++) {
            const float p0 = __expf(sc[nt][0] - nm0);
            const float p1 = __expf(sc[nt][1] - nm0);
            const float p2 = __expf(sc[nt][2] - nm1);
            const float p3 = __expf(sc[nt][3] - nm1);
            ps0 += p0 + p1; ps1 += p2 + p3;
            *(__half2*)&Ps[rA * 72 + nt * 8 + 2*tig]       = __floats2half2_rn(p0, p1);
            *(__half2*)&Ps[(rA + 8) * 72 + nt * 8 + 2*tig] = __floats2half2_rn(p2, p3);
        }
        ps0 += __shfl_xor_sync(0xffffffffu, ps0, 1);
        ps0 += __shfl_xor_sync(0xffffffffu, ps0, 2);
        ps1 += __shfl_xor_sync(0xffffffffu, ps1, 1);
        ps1 += __shfl_xor_sync(0xffffffffu, ps1, 2);

        l0 = l0 * a0 + ps0;  l1 = l1 * a1 + ps1;
        m0 = nm0;  m1 = nm1;
        #pragma unroll
        for (int nt = 0; nt < 8; nt++) {
            oacc[nt][0] *= a0; oacc[nt][1] *= a0;
            oacc[nt][2] *= a1; oacc[nt][3] *= a1;
        }
        __syncwarp();

        // ---- O += P V  (Ps rows are warp-private; no CTA sync needed) ----
        const int mi = lane >> 3, rr = lane & 7;
        #pragma unroll
        for (int kc4 = 0; kc4 < 4; kc4++) {
            const int kc = kc4 * 16;
            uint32_t af[4];
            LDMX4(af[0], af[1], af[2], af[3],
                  smem_u32(&Ps[(warp * 16 + a_row) * 72 + kc + a_col]));
            #pragma unroll
            for (int ntp = 0; ntp < 4; ntp++) {
                const int key = kc + ((mi & 1) << 3) + rr;
                const int dim = ntp * 16 + ((mi >> 1) << 3);
                uint32_t r0, r1, r2, r3;
                LDMX4_TRANS(r0, r1, r2, r3, smem_u32(&Vc[key * 72 + dim]));
                uint32_t b0[2] = {r0, r1};
                uint32_t b1[2] = {r2, r3};
                MMA_F16(oacc[2*ntp],     af, b0);
                MMA_F16(oacc[2*ntp + 1], af, b1);
            }
        }
        if (++cur >= 3) cur = 0;
        // no trailing sync: stage reuse ordered by next leading sync
    }

    const float i0 = 1.f / l0, i1 = 1.f / l1;
    #pragma unroll
    for (int nt = 0; nt < 8; nt++) {
        const int col = nt * 8 + 2 * tig;
        *(__half2*)&O[baseO + (size_t)(q0 + rA) * D_MODEL + col] =
            __floats2half2_rn(oacc[nt][0] * i0, oacc[nt][1] * i0);
        *(__half2*)&O[baseO + (size_t)(q0 + rA + 8) * D_MODEL + col] =
            __floats2half2_rn(oacc[nt][2] * i1, oacc[nt][3] * i1);
    }
}

// ---------------- launch ---------------------------------------------------
extern "C" void kernel_launch(void* const* d_in, const int* in_sizes, int n_in,
                              void* d_out, int out_size)
{
    const float* x     = (const float*)d_in[0];
    const unsigned char* mask = (const unsigned char*)d_in[1];
    const float* W_Q   = (const float*)d_in[2];
    const float* W_K   = (const float*)d_in[3];
    const float* W_V   = (const float*)d_in[4];
    const float* W_O   = (const float*)d_in[5];
    const float* W1    = (const float*)d_in[6];
    const float* b1    = (const float*)d_in[7];
    const float* W2    = (const float*)d_in[8];
    const float* b2    = (const float*)d_in[9];
    const float* g1    = (const float*)d_in[10];
    const float* beta1 = (const float*)d_in[11];
    const float* g2    = (const float*)d_in[12];
    const float* beta2 = (const float*)d_in[13];
    float* out = (float*)d_out;

    __half *h1, *qkv, *at, *h2, *f1;
    __half *wqkv, *wo, *w1, *w2;
    float *x1;
    cudaGetSymbolAddress((void**)&h1,   g_h1);
    cudaGetSymbolAddress((void**)&qkv,  g_qkv);
    cudaGetSymbolAddress((void**)&at,   g_at);
    cudaGetSymbolAddress((void**)&x1,   g_x1);
    cudaGetSymbolAddress((void**)&h2,   g_h2);
    cudaGetSymbolAddress((void**)&f1,   g_f1);
    cudaGetSymbolAddress((void**)&wqkv, g_wqkv);
    cudaGetSymbolAddress((void**)&wo,   g_wo);
    cudaGetSymbolAddress((void**)&w1,   g_w1);
    cudaGetSymbolAddress((void**)&w2,   g_w2);

    cudaFuncSetAttribute(attn_tc, cudaFuncAttributeMaxDynamicSharedMemorySize,
                         ASMEM_BYTES);
    cudaFuncSetAttribute(gemm_f16<0,1>, cudaFuncAttributeMaxDynamicSharedMemorySize, G_SMEM);
    cudaFuncSetAttribute(gemm_f16<2,0>, cudaFuncAttributeMaxDynamicSharedMemorySize, G_SMEM);
    cudaFuncSetAttribute(gemm_f16<1,1>, cudaFuncAttributeMaxDynamicSharedMemorySize, G_SMEM);
    cudaFuncSetAttribute(gemm_f16<3,0>, cudaFuncAttributeMaxDynamicSharedMemorySize, G_SMEM);

    const dim3 gQKV(D3/128,      NTOK/64);   // (24, 64)
    const dim3 gDD (D_MODEL/128, NTOK/64);   // (8, 64)
    const dim3 gDF (D_FF/128,    NTOK/64);   // (32, 64)
    const int DD4 = D_MODEL*D_MODEL/4, DF4 = D_FF*D_MODEL/4;

    // 0. weights -> fp16
    conv_qkv <<<3*DD4/256, 256>>>((const float4*)W_Q, (const float4*)W_K,
                                  (const float4*)W_V, wqkv);
    conv_rest<<<(DD4 + 2*DF4 + 255)/256, 256>>>((const float4*)W_O,
                                                (const float4*)W1,
                                                (const float4*)W2,
                                                wo, w1, w2);

    // 1. pre-LN
    ln_kernel<<<NTOK, 256>>>(x, g1, beta1, h1);
    // 2. fused QKV projection
    gemm_f16<0,1><<<gQKV, 256, G_SMEM>>>(h1, wqkv, qkv, NTOK, D3, D_MODEL, nullptr, nullptr);
    // 3. flash attention (3-stage ring)
    attn_tc<<<dim3(SEQ/128, HEADS, BATCH), 256, ASMEM_BYTES>>>(qkv, mask, at);
    // 4. output projection + residual (fp32 out)
    gemm_f16<2,0><<<gDD, 256, G_SMEM>>>(at, wo, x1, NTOK, D_MODEL, D_MODEL, nullptr, x);
    // 5. second LN
    ln_kernel<<<NTOK, 256>>>(x1, g2, beta2, h2);
    // 6. FFN1 (+b1)
    gemm_f16<1,1><<<gDF, 256, G_SMEM>>>(h2, w1, f1, NTOK, D_FF, D_MODEL, b1, nullptr);
    // 7. FFN2: relu(C + b2) + residual(x1), fp32 final
    gemm_f16<3,0><<<gDD, 256, G_SMEM>>>(f1, w2, out, NTOK, D_MODEL, D_FF, b2, x1);
}